// round 9
// baseline (speedup 1.0000x reference)
#include <cuda_runtime.h>
#include <cuda_fp16.h>
#include <math.h>

#define BATCH 32
#define HW1 960
#define NTAB 9801
#define NTHR 576
#define NW 18

// ---------------- device scratch ----------------
__device__ float g_rg[NTAB];   // AGGD r(gamma) table (monotone increasing)
__device__ float g_feats[BATCH * 100 * 36];
__device__ int g_done[BATCH];  // zero-initialized; reset by tail CTA each launch

static __device__ __forceinline__ float fsqrt_ap(float x) {
    float r; asm("sqrt.approx.f32 %0, %1;" : "=f"(r) : "f"(x)); return r;
}
static __device__ __forceinline__ float fdiv_ap(float a, float b) {
    float r; asm("div.approx.f32 %0, %1, %2;" : "=f"(r) : "f"(a), "f"(b)); return r;
}
static __device__ __forceinline__ unsigned long long pack2(float a, float b) {
    unsigned long long r;
    asm("mov.b64 %0, {%1, %2};" : "=l"(r) : "f"(a), "f"(b));
    return r;
}
static __device__ __forceinline__ void unpack2(unsigned long long p, float& a, float& b) {
    asm("mov.b64 {%0, %1}, %2;" : "=f"(a), "=f"(b) : "l"(p));
}
static __device__ __forceinline__ unsigned long long ffma2(
    unsigned long long a, unsigned long long b, unsigned long long c) {
    unsigned long long d;
    asm("fma.rn.f32x2 %0, %1, %2, %3;" : "=l"(d) : "l"(a), "l"(b), "l"(c));
    return d;
}

// ---------------- per-thread weights ----------------
static __device__ __forceinline__ void make_w7(float* w) {
    const float inv2s2 = 1.0f / (2.0f * (7.0f / 6.0f) * (7.0f / 6.0f));
    float s = 0.f;
#pragma unroll
    for (int j = 0; j < 7; j++) {
        float ax = (float)j - 3.0f;
        w[j] = expf(-ax * ax * inv2s2);
        s += w[j];
    }
    float inv = 1.0f / s;
#pragma unroll
    for (int j = 0; j < 7; j++) w[j] *= inv;
}
static __device__ __forceinline__ void make_w3(float* w) {
    float e = expf(-2.0f);
    float s = 2.f * e + 1.f;
    float inv = 1.0f / s;
    w[0] = e * inv; w[1] = inv; w[2] = e * inv;
}

// ---------------- init: AGGD r(gamma) table ----------------
__global__ void init_tables_kernel() {
    int i = blockIdx.x * blockDim.x + threadIdx.x;
    if (i < NTAB) {
        float g = fmaf((float)i, 0.001f, 0.2f);
        float inv = 1.0f / g;
        g_rg[i] = expf(2.f * lgammaf(2.f * inv) - lgammaf(inv) - lgammaf(3.f * inv));
    }
}

// Warp-cooperative argmin over monotone table; first-index tie-break.
static __device__ __forceinline__ int argmin_table_warp(float t, int lane) {
    int lo = -1, hi = NTAB;
    while (hi - lo > 1) {
        int w = hi - lo - 1;
        int pos = lo + 1 + (int)(((unsigned)lane * (unsigned)w) >> 5);
        float v = __ldg(&g_rg[pos]);
        unsigned m = __ballot_sync(0xffffffffu, v < t);
        if (m == 0u) {
            hi = lo + 1;
        } else {
            int last = 31 - __clz(m);
            int nlo = __shfl_sync(0xffffffffu, pos, last);
            int nhi = hi;
            if (m != 0xffffffffu) {
                int first = __ffs(~m) - 1;
                nhi = __shfl_sync(0xffffffffu, pos, first);
            }
            lo = nlo; hi = nhi;
        }
    }
    int j = hi;
    if (j <= 0) return 0;
    if (j >= NTAB) return NTAB - 1;
    float d0 = fabsf(__ldg(&g_rg[j - 1]) - t);
    float d1 = fabsf(__ldg(&g_rg[j]) - t);
    return (d0 <= d1) ? (j - 1) : j;
}

static __device__ __forceinline__ float to_f32(float v) { return v; }
static __device__ __forceinline__ float to_f32(__half v) { return __half2float(v); }

// ---------------- AGGD stats (row-banded, shfl neighbors, ballot counts) -------
// Warps 0..15 each own BS/16 consecutive rows; neighbors come from registers and
// warp shuffles (circular wraps handled with per-chunk fixups).
template <int BS, typename TX>
static __device__ __forceinline__ void aggd_features(
    const TX* xnb, int stride, float Nf, int b, int blk, int foff,
    int tid, float (*s_wsum)[20], float* s_tot, float* s_par) {
    const unsigned FULL = 0xffffffffu;
    constexpr int K = (BS + 31) / 32;          // col chunks: 3 (BS=96) / 2 (BS=48)
    constexpr int RPW = BS / 16;               // rows per warp (warps 0..15)
    constexpr int REM = BS & 31;               // cols in last chunk (0 => full)
    constexpr int WLANE = REM ? REM - 1 : 31;  // lane of last column in last chunk
    int warp = tid >> 5, lane = tid & 31;

    float accf[15];
#pragma unroll
    for (int k = 0; k < 15; k++) accf[k] = 0.f;
    int cnt[5] = {0, 0, 0, 0, 0};

    if (warp < 16) {
        float prv[K], cur[K];
        int r0 = warp * RPW;
        int pr = (r0 == 0) ? (BS - 1) : (r0 - 1);
        const TX* prow = xnb + pr * stride;
#pragma unroll
        for (int k = 0; k < K; k++) {
            int c = k * 32 + lane;
            prv[k] = (c < BS) ? to_f32(prow[c]) : 0.f;
        }
        for (int rr = 0; rr < RPW; rr++) {
            const TX* crow = xnb + (r0 + rr) * stride;
#pragma unroll
            for (int k = 0; k < K; k++) {
                int c = k * 32 + lane;
                cur[k] = (c < BS) ? to_f32(crow[c]) : 0.f;
            }
#pragma unroll
            for (int k = 0; k < K; k++) {
                const int lastL = (k == K - 1) ? WLANE : 31;
                const int cmsrc = (k == 0) ? K - 1 : k - 1;
                const int cmlane = (k == 0) ? WLANE : 31;
                const int cpsrc = (k == K - 1) ? 0 : k + 1;
                float upC = __shfl_up_sync(FULL, cur[k], 1);
                float upM = __shfl_up_sync(FULL, prv[k], 1);
                float dnM = __shfl_down_sync(FULL, prv[k], 1);
                float fixCmC = __shfl_sync(FULL, cur[cmsrc], cmlane);
                float fixCmM = __shfl_sync(FULL, prv[cmsrc], cmlane);
                float fixCpM = __shfl_sync(FULL, prv[cpsrc], 0);
                float cmC = (lane == 0) ? fixCmC : upC;
                float cmM = (lane == 0) ? fixCmM : upM;
                float cpM = (lane == lastL) ? fixCpM : dnM;
                float x0 = cur[k];   // 0 for inactive lanes -> zero contributions
                float ys[5];
                ys[0] = x0;
                ys[1] = x0 * cmC;    // shift (0,1): x[r][c]*x[r][c-1]
                ys[2] = x0 * prv[k]; // shift (1,0): x[r][c]*x[r-1][c]
                ys[3] = x0 * cmM;    // shift (1,1)
                ys[4] = x0 * cpM;    // shift (1,-1)
#pragma unroll
                for (int s = 0; s < 5; s++) {
                    float v = ys[s];
                    accf[s * 3 + 0] = fmaf(v, v, accf[s * 3 + 0]);        // S2
                    accf[s * 3 + 1] = fmaf(v, fabsf(v), accf[s * 3 + 1]); // SV
                    accf[s * 3 + 2] += fabsf(v);                           // SA
                    cnt[s] += __popc(__ballot_sync(FULL, v > 0.f));        // CP
                }
            }
#pragma unroll
            for (int k = 0; k < K; k++) prv[k] = cur[k];
        }
    }
#pragma unroll
    for (int k = 0; k < 15; k++)
#pragma unroll
        for (int off = 16; off > 0; off >>= 1)
            accf[k] += __shfl_down_sync(0xffffffffu, accf[k], off);
    if (lane == 0) {
#pragma unroll
        for (int k = 0; k < 15; k++) s_wsum[warp][k] = accf[k];
#pragma unroll
        for (int s = 0; s < 5; s++) s_wsum[warp][15 + s] = (float)cnt[s];  // warp-uniform
    }
    __syncthreads();
    if (tid < 20) {
        float s = 0.f;
        for (int wi = 0; wi < NW; wi++) s += s_wsum[wi][tid];
        s_tot[tid] = s;
    }
    __syncthreads();
    if (tid < 5) {
        float S2 = s_tot[tid * 3 + 0], SV = s_tot[tid * 3 + 1], SA = s_tot[tid * 3 + 2];
        float CP = s_tot[15 + tid];
        float SP2 = 0.5f * (S2 + SV);
        float SN2 = fmaxf(0.5f * (S2 - SV), 0.f);
        float CN = Nf - CP;
        float lstd = sqrtf(SN2 / fmaxf(CN, 1.f));
        float rstd = sqrtf(SP2 / fmaxf(CP, 1.f));
        s_par[5 + tid] = lstd;
        s_par[10 + tid] = rstd;
        float gh = lstd / fmaxf(rstd, 1e-12f);
        float ma = SA / Nf, ms = S2 / Nf;
        float rhat = (ma * ma) / fmaxf(ms, 1e-12f);
        float gh2 = gh * gh;
        s_par[tid] = rhat * (gh2 * gh + 1.f) * (gh + 1.f) / ((gh2 + 1.f) * (gh2 + 1.f));
    }
    __syncthreads();
    if (warp < 5) {
        int idxm = argmin_table_warp(s_par[warp], lane);
        if (lane == 0) {
            float alpha = (float)(0.2 + 0.001 * (double)idxm);
            float conv = expf(0.5f * (lgammaf(1.f / alpha) - lgammaf(3.f / alpha)));
            float bl = s_par[5 + warp] * conv, br = s_par[10 + warp] * conv;
            float* fo = &g_feats[((size_t)b * 100 + blk) * 36 + foff];
            if (warp == 0) {
                fo[0] = alpha;
                fo[1] = 0.5f * (bl + br);
            } else {
                int o = 2 + (warp - 1) * 4;
                fo[o] = alpha;
                fo[o + 1] = (br - bl) * expf(lgammaf(2.f / alpha) - lgammaf(1.f / alpha));
                fo[o + 2] = bl;
                fo[o + 3] = br;
            }
            __threadfence();  // release this block's feature writes before counter bump
        }
    }
}

// ---------------- unified feature kernel with fused per-image finalization -----
__global__ __launch_bounds__(NTHR, 3) void feat_kernel(
    const float* __restrict__ X, const float* __restrict__ mu_pris,
    const float* __restrict__ cov_pris, float* __restrict__ out) {
    extern __shared__ float sm[];
    __shared__ float s_wsum[NW][20];
    __shared__ float s_tot[20];
    __shared__ float s_par[15];
    __shared__ int s_tail;
    int tid = threadIdx.x, warp = tid >> 5, lane = tid & 31;
    int id = blockIdx.x;
    int b;

    if (id < 3200) {
        // -------- scale 1: 96x96 --------
        b = id / 100;
        int blk = id - 100 * b;
        int by0 = (blk / 10) * 96, bx0 = (blk % 10) * 96;
        const int TS = 104;
        float* T = sm;                          // 102 x 104
        __half* xn = (__half*)(sm + 102 * TS);  // 96 x 96 fp16
        const float* im = X + (size_t)b * HW1 * HW1;

        if (bx0 != 0 && bx0 != 864) {
            int astart = bx0 - 4;
            for (int r = warp; r < 102; r += NW) {
                int gy = by0 + r - 3; gy = gy < 0 ? 0 : (gy > 959 ? 959 : gy);
                const float4* rowp = (const float4*)(im + (size_t)gy * HW1 + astart);
                if (lane < 26) {
                    float4 v = __ldg(rowp + lane);
                    *(float4*)&T[r * TS + 4 * lane] = v;
                }
            }
        } else {
            for (int r = warp; r < 102; r += NW) {
                int gy = by0 + r - 3; gy = gy < 0 ? 0 : (gy > 959 ? 959 : gy);
                const float* rowp = im + (size_t)gy * HW1;
#pragma unroll
                for (int k = 0; k < 4; k++) {
                    int c = lane + 32 * k;
                    if (k < 3 || c < 102) {
                        int gx = bx0 + c - 3; gx = gx < 0 ? 0 : (gx > 959 ? 959 : gx);
                        T[r * TS + c + 1] = __ldg(rowp + gx);
                    }
                }
            }
        }
        float w7[7]; make_w7(w7);
        unsigned long long wp[7];
#pragma unroll
        for (int t = 0; t < 7; t++) wp[t] = pack2(w7[t], w7[t]);
        __syncthreads();

        int seg = warp / 3, strip = warp - seg * 3;
        int c = strip * 32 + lane;
        int r0 = seg * 16;
        unsigned long long ring[7];
#pragma unroll
        for (int j = 0; j < 22; j++) {
            const float* row = &T[(r0 + j) * TS + c + 1];
            unsigned long long acc = 0ull;
#pragma unroll
            for (int t = 0; t < 7; t++) {
                float v = row[t];
                acc = ffma2(wp[t], pack2(v, v * v), acc);
            }
            ring[j % 7] = acc;
            if (j >= 6) {
                unsigned long long me = 0ull;
#pragma unroll
                for (int i = 0; i < 7; i++) me = ffma2(wp[i], ring[(j - 6 + i) % 7], me);
                float mu, e2; unpack2(me, mu, e2);
                float var = fmaxf(fabsf(e2 - mu * mu), 1e-30f);
                float sig = fsqrt_ap(var);
                int rloc = r0 + j - 6;
                float x = T[(rloc + 3) * TS + (c + 4)];
                xn[rloc * 96 + c] = __float2half(fdiv_ap(x - mu, sig + 1.f));
            }
        }
        __syncthreads();
        aggd_features<96>(xn, 96, 9216.f, b, blk, 0, tid, s_wsum, s_tot, s_par);
    } else {
        // -------- scale 2: fused downsample + 48x48 --------
        int id2 = id - 3200;
        b = id2 / 100;
        int blk = id2 - 100 * b;
        int by0 = (blk / 10) * 48, bx0 = (blk % 10) * 48;
        float* Dh = sm;                    // 109 x 54
        float* T2 = Dh + 109 * 54;         // 54 x 54 (center -> xn)
        float* rX = T2 + 54 * 54;          // 54 x 48
        float* rX2 = rX + 54 * 48;         // 54 x 48
        const float* im = X + (size_t)b * HW1 * HW1;
        float w[7]; make_w7(w);
        float w3v[3]; make_w3(w3v);
        float w3a = w3v[0], w3b = w3v[1], w3c = w3v[2];
        int rbase = 2 * by0 - 7;

        if (bx0 != 0 && bx0 != 432) {
            int astart2 = 2 * bx0 - 8;
            for (int i = warp; i < 109; i += NW) {
                int ri = rbase + i;
                if (ri >= 0 && ri < 960) {
                    float4 v = make_float4(0.f, 0.f, 0.f, 0.f);
                    if (lane < 28)
                        v = __ldg((const float4*)(im + (size_t)ri * HW1 + astart2) + lane);
                    float nx = __shfl_down_sync(0xffffffffu, v.x, 1);
                    float ny = __shfl_down_sync(0xffffffffu, v.y, 1);
                    if (lane < 27) {
                        float o0 = fmaf(w3a, v.y, fmaf(w3b, v.z, w3c * v.w));
                        float o1 = fmaf(w3a, v.w, fmaf(w3b, nx, w3c * ny));
                        *(float2*)&Dh[i * 54 + 2 * lane] = make_float2(o0, o1);
                    }
                } else {
                    for (int k2 = lane; k2 < 54; k2 += 32) Dh[i * 54 + k2] = 0.f;
                }
            }
        } else {
            for (int idx = tid; idx < 109 * 54; idx += NTHR) {
                int i = idx / 54, cc = idx - 54 * i;
                int ri = rbase + i;
                float s = 0.f;
                if (ri >= 0 && ri < 960) {
                    int gxc = bx0 + cc - 3; gxc = gxc < 0 ? 0 : (gxc > 479 ? 479 : gxc);
                    int sx = 2 * gxc - 1;
                    const float* rp = &im[(size_t)ri * HW1];
                    if (sx >= 0) s = fmaf(w3a, __ldg(&rp[sx]), s);
                    s = fmaf(w3b, __ldg(&rp[sx + 1]), s);
                    if (sx + 2 < 960) s = fmaf(w3c, __ldg(&rp[sx + 2]), s);
                }
                Dh[idx] = s;
            }
        }
        __syncthreads();
        for (int idx = tid; idx < 54 * 54; idx += NTHR) {
            int r = idx / 54, cc = idx - 54 * r;
            int gyc = by0 + r - 3; gyc = gyc < 0 ? 0 : (gyc > 479 ? 479 : gyc);
            int row0 = 2 * (gyc - by0) + 6;
            const float* p = &Dh[row0 * 54 + cc];
            T2[idx] = fmaf(w3a, p[0], fmaf(w3b, p[54], w3c * p[108]));
        }
        __syncthreads();
        for (int idx = tid; idx < 54 * 48; idx += NTHR) {
            int r = idx / 48, cc = idx - 48 * r;
            const float* tr = &T2[r * 54 + cc];
            float a1 = 0.f, a2 = 0.f;
#pragma unroll
            for (int t = 0; t < 7; t++) {
                float v = tr[t];
                a1 = fmaf(w[t], v, a1);
                a2 = fmaf(w[t], v * v, a2);
            }
            rX[idx] = a1; rX2[idx] = a2;
        }
        __syncthreads();
        for (int idx = tid; idx < 48 * 48; idx += NTHR) {
            int r = idx / 48, cc = idx - 48 * r;
            float mu = 0.f, e2 = 0.f;
#pragma unroll
            for (int i = 0; i < 7; i++) {
                mu = fmaf(w[i], rX[(r + i) * 48 + cc], mu);
                e2 = fmaf(w[i], rX2[(r + i) * 48 + cc], e2);
            }
            float var = fmaxf(fabsf(e2 - mu * mu), 1e-30f);
            float sig = fsqrt_ap(var);
            int ctr = (r + 3) * 54 + cc + 3;
            T2[ctr] = fdiv_ap(T2[ctr] - mu, sig + 1.f);
        }
        __syncthreads();
        aggd_features<48>(&T2[3 * 54 + 3], 54, 2304.f, b, blk, 18, tid, s_wsum, s_tot, s_par);
    }

    // -------- fused finalization: last CTA of image b does cov + Cholesky --------
    __syncthreads();
    if (tid == 0) s_tail = (atomicAdd(&g_done[b], 1) == 199) ? 1 : 0;
    __syncthreads();
    if (s_tail) {
        if (tid == 0) g_done[b] = 0;  // reset for next launch
        float* sd = sm;               // 3600
        float* sM = sm + 3600;        // 36*37
        float* smu = sm + 3600 + 36 * 37;
        float* sdiff = smu + 36;
        float* sz = sdiff + 36;
        const float* fb = &g_feats[(size_t)b * 3600];
        for (int i = tid; i < 3600; i += NTHR) sd[i] = __ldcg(&fb[i]);
        __syncthreads();
        if (tid < 36) {
            float s = 0.f;
            for (int n = 0; n < 100; n++) s += sd[n * 36 + tid];
            float m = s / 100.0f;
            smu[tid] = m;
            sdiff[tid] = mu_pris[tid] - m;
        }
        __syncthreads();
        for (int idx = tid; idx < 1296; idx += NTHR) {
            int f = idx / 36, g = idx - f * 36;
            if (g < f) continue;
            float mf = smu[f], mg = smu[g];
            float a0 = 0.f, a1 = 0.f, a2 = 0.f, a3 = 0.f;
            for (int n = 0; n < 100; n += 4) {
                a0 = fmaf(sd[n * 36 + f] - mf, sd[n * 36 + g] - mg, a0);
                a1 = fmaf(sd[(n + 1) * 36 + f] - mf, sd[(n + 1) * 36 + g] - mg, a1);
                a2 = fmaf(sd[(n + 2) * 36 + f] - mf, sd[(n + 2) * 36 + g] - mg, a2);
                a3 = fmaf(sd[(n + 3) * 36 + f] - mf, sd[(n + 3) * 36 + g] - mg, a3);
            }
            float s = ((a0 + a1) + (a2 + a3)) / 99.0f;
            float m = 0.5f * (cov_pris[idx] + s);
            sM[f * 37 + g] = m;
            sM[g * 37 + f] = m;
        }
        __syncthreads();
        if (tid < 32) {
            for (int j = 0; j < 36; j++) {
                float pd = 0.f, pz = 0.f;
                for (int k = lane; k < j; k += 32) {
                    float l = sM[j * 37 + k];
                    pd = fmaf(l, l, pd);
                    pz = fmaf(l, sz[k], pz);
                }
#pragma unroll
                for (int off = 16; off > 0; off >>= 1) {
                    pd += __shfl_down_sync(0xffffffffu, pd, off);
                    pz += __shfl_down_sync(0xffffffffu, pz, off);
                }
                if (lane == 0) {
                    float d = sqrtf(fmaxf(sM[j * 37 + j] - pd, 1e-20f));
                    sM[j * 37 + j] = d;
                    sz[j] = (sdiff[j] - pz) / d;
                }
                __syncwarp();
                float dj = sM[j * 37 + j];
                for (int i = j + 1 + lane; i < 36; i += 32) {
                    float s = sM[i * 37 + j];
                    for (int k = 0; k < j; k++) s -= sM[i * 37 + k] * sM[j * 37 + k];
                    sM[i * 37 + j] = s / dj;
                }
                __syncwarp();
            }
            if (lane == 0) {
                float q = 0.f;
                for (int i = 0; i < 36; i++) q += sz[i] * sz[i];
                out[b] = sqrtf(fmaxf(q, 0.f));
            }
        }
    }
}

// ---------------- launch ----------------
extern "C" void kernel_launch(void* const* d_in, const int* in_sizes, int n_in,
                              void* d_out, int out_size) {
    (void)in_sizes; (void)n_in; (void)out_size;
    const float* X = (const float*)d_in[0];
    const float* mu_pris = (const float*)d_in[1];
    const float* cov_pris = (const float*)d_in[2];
    float* out = (float*)d_out;

    const size_t smB = (size_t)(102 * 104) * sizeof(float) + (size_t)(96 * 96) * sizeof(__half);
    cudaFuncSetAttribute(feat_kernel, cudaFuncAttributeMaxDynamicSharedMemorySize, (int)smB);

    init_tables_kernel<<<(NTAB + 511) / 512, 512>>>();
    feat_kernel<<<6400, NTHR, smB>>>(X, mu_pris, cov_pris, out);
}

// round 11
// speedup vs baseline: 1.1281x; 1.1281x over previous
#include <cuda_runtime.h>
#include <cuda_fp16.h>
#include <math.h>

#define BATCH 32
#define HW1 960
#define NTAB 9801
#define NTHR 576
#define NW 18

// ---------------- device scratch ----------------
__device__ float g_rg[NTAB];   // AGGD r(gamma) table (monotone increasing)
__device__ float g_feats[BATCH * 100 * 36];
__device__ int g_done[BATCH];  // zero-init; tail CTA resets its slot each launch

static __device__ __forceinline__ float fsqrt_ap(float x) {
    float r; asm("sqrt.approx.f32 %0, %1;" : "=f"(r) : "f"(x)); return r;
}
static __device__ __forceinline__ float fdiv_ap(float a, float b) {
    float r; asm("div.approx.f32 %0, %1, %2;" : "=f"(r) : "f"(a), "f"(b)); return r;
}
static __device__ __forceinline__ unsigned long long pack2(float a, float b) {
    unsigned long long r;
    asm("mov.b64 %0, {%1, %2};" : "=l"(r) : "f"(a), "f"(b));
    return r;
}
static __device__ __forceinline__ void unpack2(unsigned long long p, float& a, float& b) {
    asm("mov.b64 {%0, %1}, %2;" : "=f"(a), "=f"(b) : "l"(p));
}
static __device__ __forceinline__ unsigned long long ffma2(
    unsigned long long a, unsigned long long b, unsigned long long c) {
    unsigned long long d;
    asm("fma.rn.f32x2 %0, %1, %2, %3;" : "=l"(d) : "l"(a), "l"(b), "l"(c));
    return d;
}

// ---------------- per-thread weights ----------------
static __device__ __forceinline__ void make_w7(float* w) {
    const float inv2s2 = 1.0f / (2.0f * (7.0f / 6.0f) * (7.0f / 6.0f));
    float s = 0.f;
#pragma unroll
    for (int j = 0; j < 7; j++) {
        float ax = (float)j - 3.0f;
        w[j] = expf(-ax * ax * inv2s2);
        s += w[j];
    }
    float inv = 1.0f / s;
#pragma unroll
    for (int j = 0; j < 7; j++) w[j] *= inv;
}
static __device__ __forceinline__ void make_w3(float* w) {
    float e = expf(-2.0f);
    float s = 2.f * e + 1.f;
    float inv = 1.0f / s;
    w[0] = e * inv; w[1] = inv; w[2] = e * inv;
}

// ---------------- init: AGGD r(gamma) table ----------------
__global__ void init_tables_kernel() {
    int i = blockIdx.x * blockDim.x + threadIdx.x;
    if (i < NTAB) {
        float g = fmaf((float)i, 0.001f, 0.2f);
        float inv = 1.0f / g;
        g_rg[i] = expf(2.f * lgammaf(2.f * inv) - lgammaf(inv) - lgammaf(3.f * inv));
    }
}

// Warp-cooperative argmin over monotone table; first-index tie-break.
static __device__ __forceinline__ int argmin_table_warp(float t, int lane) {
    int lo = -1, hi = NTAB;
    while (hi - lo > 1) {
        int w = hi - lo - 1;
        int pos = lo + 1 + (int)(((unsigned)lane * (unsigned)w) >> 5);
        float v = __ldg(&g_rg[pos]);
        unsigned m = __ballot_sync(0xffffffffu, v < t);
        if (m == 0u) {
            hi = lo + 1;
        } else {
            int last = 31 - __clz(m);
            int nlo = __shfl_sync(0xffffffffu, pos, last);
            int nhi = hi;
            if (m != 0xffffffffu) {
                int first = __ffs(~m) - 1;
                nhi = __shfl_sync(0xffffffffu, pos, first);
            }
            lo = nlo; hi = nhi;
        }
    }
    int j = hi;
    if (j <= 0) return 0;
    if (j >= NTAB) return NTAB - 1;
    float d0 = fabsf(__ldg(&g_rg[j - 1]) - t);
    float d1 = fabsf(__ldg(&g_rg[j]) - t);
    return (d0 <= d1) ? (j - 1) : j;
}

// ---------------- AGGD stats: half2 pair loads, predicated counts ----------------
// xnb: fp16 BSxBS block (row stride BS halves, 4-byte aligned rows).
// Each lane owns a column pair; 5 LDS per 2 elements; no shuffles in the hot loop.
template <int BS>
static __device__ __forceinline__ void aggd_features(
    const __half* xnb, float Nf, int b, int blk, int foff,
    int tid, float (*s_wsum)[20], float* s_tot, float* s_par) {
    constexpr int H2 = BS / 2;                 // pairs per row: 48 / 24
    constexpr int NCH = (H2 + 31) / 32;        // pair chunks: 2 / 1
    int warp = tid >> 5, lane = tid & 31;

    float accf[15];
#pragma unroll
    for (int k = 0; k < 15; k++) accf[k] = 0.f;
    float cnt[5];
#pragma unroll
    for (int k = 0; k < 5; k++) cnt[k] = 0.f;

    for (int r = warp; r < BS; r += NW) {
        int rm = (r == 0) ? (BS - 1) : (r - 1);
        const __half* rowC = xnb + r * BS;
        const __half* rowM = xnb + rm * BS;
#pragma unroll
        for (int k = 0; k < NCH; k++) {
            int p = k * 32 + lane;
            bool act = ((H2 % 32) == 0) || (p < H2);
            int ps = act ? p : 0;
            int c0 = 2 * ps;
            int cmi = (ps == 0) ? (BS - 1) : (c0 - 1);
            int cpi = (ps == H2 - 1) ? 0 : (c0 + 2);
            float2 fC = __half22float2(*(const half2*)(rowC + c0));
            float2 fM = __half22float2(*(const half2*)(rowM + c0));
            float cmC = __half2float(rowC[cmi]);
            float cmM = __half2float(rowM[cmi]);
            float cpM = __half2float(rowM[cpi]);
            if (!act) { fC.x = 0.f; fC.y = 0.f; }  // x factor=0 -> zero contributions
            // element c0
            {
                float x0 = fC.x;
                float ys[5];
                ys[0] = x0;
                ys[1] = x0 * cmC;   // shift (0,1)
                ys[2] = x0 * fM.x;  // shift (1,0)
                ys[3] = x0 * cmM;   // shift (1,1)
                ys[4] = x0 * fM.y;  // shift (1,-1)
#pragma unroll
                for (int s = 0; s < 5; s++) {
                    float v = ys[s], fa = fabsf(v);
                    accf[s * 3 + 0] = fmaf(v, v, accf[s * 3 + 0]);
                    accf[s * 3 + 1] = fmaf(v, fa, accf[s * 3 + 1]);
                    accf[s * 3 + 2] += fa;
                    if (v > 0.f) cnt[s] += 1.f;
                }
            }
            // element c0+1
            {
                float x1 = fC.y;
                float ys[5];
                ys[0] = x1;
                ys[1] = x1 * fC.x;
                ys[2] = x1 * fM.y;
                ys[3] = x1 * fM.x;
                ys[4] = x1 * cpM;
#pragma unroll
                for (int s = 0; s < 5; s++) {
                    float v = ys[s], fa = fabsf(v);
                    accf[s * 3 + 0] = fmaf(v, v, accf[s * 3 + 0]);
                    accf[s * 3 + 1] = fmaf(v, fa, accf[s * 3 + 1]);
                    accf[s * 3 + 2] += fa;
                    if (v > 0.f) cnt[s] += 1.f;
                }
            }
        }
    }
#pragma unroll
    for (int k = 0; k < 15; k++)
#pragma unroll
        for (int off = 16; off > 0; off >>= 1)
            accf[k] += __shfl_down_sync(0xffffffffu, accf[k], off);
#pragma unroll
    for (int k = 0; k < 5; k++)
#pragma unroll
        for (int off = 16; off > 0; off >>= 1)
            cnt[k] += __shfl_down_sync(0xffffffffu, cnt[k], off);
    if (lane == 0) {
#pragma unroll
        for (int k = 0; k < 15; k++) s_wsum[warp][k] = accf[k];
#pragma unroll
        for (int s = 0; s < 5; s++) s_wsum[warp][15 + s] = cnt[s];
    }
    __syncthreads();
    if (tid < 20) {
        float s = 0.f;
        for (int wi = 0; wi < NW; wi++) s += s_wsum[wi][tid];
        s_tot[tid] = s;
    }
    __syncthreads();
    if (tid < 5) {
        float S2 = s_tot[tid * 3 + 0], SV = s_tot[tid * 3 + 1], SA = s_tot[tid * 3 + 2];
        float CP = s_tot[15 + tid];
        float SP2 = 0.5f * (S2 + SV);
        float SN2 = fmaxf(0.5f * (S2 - SV), 0.f);
        float CN = Nf - CP;
        float lstd = sqrtf(SN2 / fmaxf(CN, 1.f));
        float rstd = sqrtf(SP2 / fmaxf(CP, 1.f));
        s_par[5 + tid] = lstd;
        s_par[10 + tid] = rstd;
        float gh = lstd / fmaxf(rstd, 1e-12f);
        float ma = SA / Nf, ms = S2 / Nf;
        float rhat = (ma * ma) / fmaxf(ms, 1e-12f);
        float gh2 = gh * gh;
        s_par[tid] = rhat * (gh2 * gh + 1.f) * (gh + 1.f) / ((gh2 + 1.f) * (gh2 + 1.f));
    }
    __syncthreads();
    if (warp < 5) {
        int idxm = argmin_table_warp(s_par[warp], lane);
        if (lane == 0) {
            float alpha = (float)(0.2 + 0.001 * (double)idxm);
            float conv = expf(0.5f * (lgammaf(1.f / alpha) - lgammaf(3.f / alpha)));
            float bl = s_par[5 + warp] * conv, br = s_par[10 + warp] * conv;
            float* fo = &g_feats[((size_t)b * 100 + blk) * 36 + foff];
            if (warp == 0) {
                fo[0] = alpha;
                fo[1] = 0.5f * (bl + br);
            } else {
                int o = 2 + (warp - 1) * 4;
                fo[o] = alpha;
                fo[o + 1] = (br - bl) * expf(lgammaf(2.f / alpha) - lgammaf(1.f / alpha));
                fo[o + 2] = bl;
                fo[o + 3] = br;
            }
            __threadfence();  // release feature writes before this CTA's counter bump
        }
    }
}

// ---------------- unified feature kernel with fused per-image finalization -----
__global__ __launch_bounds__(NTHR, 3) void feat_kernel(
    const float* __restrict__ X, const float* __restrict__ mu_pris,
    const float* __restrict__ cov_pris, float* __restrict__ out) {
    extern __shared__ float sm[];
    __shared__ float s_wsum[NW][20];
    __shared__ float s_tot[20];
    __shared__ float s_par[15];
    __shared__ int s_tail;
    int tid = threadIdx.x, warp = tid >> 5, lane = tid & 31;
    int id = blockIdx.x;
    int b;

    if (id < 3200) {
        // -------- scale 1: 96x96 --------
        b = id / 100;
        int blk = id - 100 * b;
        int by0 = (blk / 10) * 96, bx0 = (blk % 10) * 96;
        const int TS = 104;
        float* T = sm;                          // 102 x 104
        __half* xn = (__half*)(sm + 102 * TS);  // 96 x 96 fp16
        const float* im = X + (size_t)b * HW1 * HW1;

        if (bx0 != 0 && bx0 != 864) {
            int astart = bx0 - 4;
            for (int r = warp; r < 102; r += NW) {
                int gy = by0 + r - 3; gy = gy < 0 ? 0 : (gy > 959 ? 959 : gy);
                const float4* rowp = (const float4*)(im + (size_t)gy * HW1 + astart);
                if (lane < 26) {
                    float4 v = __ldg(rowp + lane);
                    *(float4*)&T[r * TS + 4 * lane] = v;
                }
            }
        } else {
            for (int r = warp; r < 102; r += NW) {
                int gy = by0 + r - 3; gy = gy < 0 ? 0 : (gy > 959 ? 959 : gy);
                const float* rowp = im + (size_t)gy * HW1;
#pragma unroll
                for (int k = 0; k < 4; k++) {
                    int c = lane + 32 * k;
                    if (k < 3 || c < 102) {
                        int gx = bx0 + c - 3; gx = gx < 0 ? 0 : (gx > 959 ? 959 : gx);
                        T[r * TS + c + 1] = __ldg(rowp + gx);
                    }
                }
            }
        }
        float w7[7]; make_w7(w7);
        unsigned long long wp[7];
#pragma unroll
        for (int t = 0; t < 7; t++) wp[t] = pack2(w7[t], w7[t]);
        __syncthreads();

        int seg = warp / 3, strip = warp - seg * 3;
        int c = strip * 32 + lane;
        int r0 = seg * 16;
        unsigned long long ring[7];
#pragma unroll
        for (int j = 0; j < 22; j++) {
            const float* row = &T[(r0 + j) * TS + c + 1];
            unsigned long long acc = 0ull;
#pragma unroll
            for (int t = 0; t < 7; t++) {
                float v = row[t];
                acc = ffma2(wp[t], pack2(v, v * v), acc);
            }
            ring[j % 7] = acc;
            if (j >= 6) {
                unsigned long long me = 0ull;
#pragma unroll
                for (int i = 0; i < 7; i++) me = ffma2(wp[i], ring[(j - 6 + i) % 7], me);
                float mu, e2; unpack2(me, mu, e2);
                float var = fmaxf(fabsf(e2 - mu * mu), 1e-30f);
                float sig = fsqrt_ap(var);
                int rloc = r0 + j - 6;
                float x = T[(rloc + 3) * TS + (c + 4)];
                xn[rloc * 96 + c] = __float2half(fdiv_ap(x - mu, sig + 1.f));
            }
        }
        __syncthreads();
        aggd_features<96>(xn, 9216.f, b, blk, 0, tid, s_wsum, s_tot, s_par);
    } else {
        // -------- scale 2: fused downsample + 48x48, xn stored fp16 --------
        int id2 = id - 3200;
        b = id2 / 100;
        int blk = id2 - 100 * b;
        int by0 = (blk / 10) * 48, bx0 = (blk % 10) * 48;
        float* Dh = sm;                    // 109 x 54 (reused as xnH after vert conv)
        float* T2 = Dh + 109 * 54;         // 54 x 54 downsampled tile
        float* rX = T2 + 54 * 54;          // 54 x 48
        float* rX2 = rX + 54 * 48;         // 54 x 48
        __half* xnH = (__half*)Dh;         // 48 x 48 fp16 (alias of dead Dh region)
        const float* im = X + (size_t)b * HW1 * HW1;
        float w[7]; make_w7(w);
        float w3v[3]; make_w3(w3v);
        float w3a = w3v[0], w3b = w3v[1], w3c = w3v[2];
        int rbase = 2 * by0 - 7;

        if (bx0 != 0 && bx0 != 432) {
            int astart2 = 2 * bx0 - 8;
            for (int i = warp; i < 109; i += NW) {
                int ri = rbase + i;
                if (ri >= 0 && ri < 960) {
                    float4 v = make_float4(0.f, 0.f, 0.f, 0.f);
                    if (lane < 28)
                        v = __ldg((const float4*)(im + (size_t)ri * HW1 + astart2) + lane);
                    float nx = __shfl_down_sync(0xffffffffu, v.x, 1);
                    float ny = __shfl_down_sync(0xffffffffu, v.y, 1);
                    if (lane < 27) {
                        float o0 = fmaf(w3a, v.y, fmaf(w3b, v.z, w3c * v.w));
                        float o1 = fmaf(w3a, v.w, fmaf(w3b, nx, w3c * ny));
                        *(float2*)&Dh[i * 54 + 2 * lane] = make_float2(o0, o1);
                    }
                } else {
                    for (int k2 = lane; k2 < 54; k2 += 32) Dh[i * 54 + k2] = 0.f;
                }
            }
        } else {
            for (int idx = tid; idx < 109 * 54; idx += NTHR) {
                int i = idx / 54, cc = idx - 54 * i;
                int ri = rbase + i;
                float s = 0.f;
                if (ri >= 0 && ri < 960) {
                    int gxc = bx0 + cc - 3; gxc = gxc < 0 ? 0 : (gxc > 479 ? 479 : gxc);
                    int sx = 2 * gxc - 1;
                    const float* rp = &im[(size_t)ri * HW1];
                    if (sx >= 0) s = fmaf(w3a, __ldg(&rp[sx]), s);
                    s = fmaf(w3b, __ldg(&rp[sx + 1]), s);
                    if (sx + 2 < 960) s = fmaf(w3c, __ldg(&rp[sx + 2]), s);
                }
                Dh[idx] = s;
            }
        }
        __syncthreads();
        for (int idx = tid; idx < 54 * 54; idx += NTHR) {
            int r = idx / 54, cc = idx - 54 * r;
            int gyc = by0 + r - 3; gyc = gyc < 0 ? 0 : (gyc > 479 ? 479 : gyc);
            int row0 = 2 * (gyc - by0) + 6;
            const float* p = &Dh[row0 * 54 + cc];
            T2[idx] = fmaf(w3a, p[0], fmaf(w3b, p[54], w3c * p[108]));
        }
        __syncthreads();
        for (int idx = tid; idx < 54 * 48; idx += NTHR) {
            int r = idx / 48, cc = idx - 48 * r;
            const float* tr = &T2[r * 54 + cc];
            float a1 = 0.f, a2 = 0.f;
#pragma unroll
            for (int t = 0; t < 7; t++) {
                float v = tr[t];
                a1 = fmaf(w[t], v, a1);
                a2 = fmaf(w[t], v * v, a2);
            }
            rX[idx] = a1; rX2[idx] = a2;
        }
        __syncthreads();  // Dh no longer needed; safe to overwrite as xnH below
        for (int idx = tid; idx < 48 * 48; idx += NTHR) {
            int r = idx / 48, cc = idx - 48 * r;
            float mu = 0.f, e2 = 0.f;
#pragma unroll
            for (int i = 0; i < 7; i++) {
                mu = fmaf(w[i], rX[(r + i) * 48 + cc], mu);
                e2 = fmaf(w[i], rX2[(r + i) * 48 + cc], e2);
            }
            float var = fmaxf(fabsf(e2 - mu * mu), 1e-30f);
            float sig = fsqrt_ap(var);
            float x = T2[(r + 3) * 54 + cc + 3];
            xnH[r * 48 + cc] = __float2half(fdiv_ap(x - mu, sig + 1.f));
        }
        __syncthreads();
        aggd_features<48>(xnH, 2304.f, b, blk, 18, tid, s_wsum, s_tot, s_par);
    }

    // -------- fused finalization: last CTA of image b does cov + Cholesky --------
    __syncthreads();
    if (tid == 0) s_tail = (atomicAdd(&g_done[b], 1) == 199) ? 1 : 0;
    __syncthreads();
    if (s_tail) {
        if (tid == 0) g_done[b] = 0;  // reset slot up-front for next graph replay
        float* sd = sm;               // 3600
        float* sM = sm + 3600;        // 36*37
        float* smu = sm + 3600 + 36 * 37;
        float* sdiff = smu + 36;
        float* sz = sdiff + 36;
        const float* fb = &g_feats[(size_t)b * 3600];
        for (int i = tid; i < 3600; i += NTHR) sd[i] = __ldcg(&fb[i]);
        __syncthreads();
        if (tid < 36) {
            float s = 0.f;
            for (int n = 0; n < 100; n++) s += sd[n * 36 + tid];
            float m = s / 100.0f;
            smu[tid] = m;
            sdiff[tid] = mu_pris[tid] - m;
        }
        __syncthreads();
        for (int idx = tid; idx < 1296; idx += NTHR) {
            int f = idx / 36, g = idx - f * 36;
            if (g < f) continue;
            float mf = smu[f], mg = smu[g];
            float a0 = 0.f, a1 = 0.f, a2 = 0.f, a3 = 0.f;
            for (int n = 0; n < 100; n += 4) {
                a0 = fmaf(sd[n * 36 + f] - mf, sd[n * 36 + g] - mg, a0);
                a1 = fmaf(sd[(n + 1) * 36 + f] - mf, sd[(n + 1) * 36 + g] - mg, a1);
                a2 = fmaf(sd[(n + 2) * 36 + f] - mf, sd[(n + 2) * 36 + g] - mg, a2);
                a3 = fmaf(sd[(n + 3) * 36 + f] - mf, sd[(n + 3) * 36 + g] - mg, a3);
            }
            float s = ((a0 + a1) + (a2 + a3)) / 99.0f;
            float m = 0.5f * (cov_pris[idx] + s);
            sM[f * 37 + g] = m;
            sM[g * 37 + f] = m;
        }
        __syncthreads();
        if (tid < 32) {
            for (int j = 0; j < 36; j++) {
                float pd = 0.f, pz = 0.f;
                for (int k = lane; k < j; k += 32) {
                    float l = sM[j * 37 + k];
                    pd = fmaf(l, l, pd);
                    pz = fmaf(l, sz[k], pz);
                }
#pragma unroll
                for (int off = 16; off > 0; off >>= 1) {
                    pd += __shfl_down_sync(0xffffffffu, pd, off);
                    pz += __shfl_down_sync(0xffffffffu, pz, off);
                }
                if (lane == 0) {
                    float d = sqrtf(fmaxf(sM[j * 37 + j] - pd, 1e-20f));
                    sM[j * 37 + j] = d;
                    sz[j] = (sdiff[j] - pz) / d;
                }
                __syncwarp();
                float dj = sM[j * 37 + j];
                for (int i = j + 1 + lane; i < 36; i += 32) {
                    float s = sM[i * 37 + j];
                    for (int k = 0; k < j; k++) s -= sM[i * 37 + k] * sM[j * 37 + k];
                    sM[i * 37 + j] = s / dj;
                }
                __syncwarp();
            }
            if (lane == 0) {
                float q = 0.f;
                for (int i = 0; i < 36; i++) q += sz[i] * sz[i];
                out[b] = sqrtf(fmaxf(q, 0.f));
            }
        }
    }
}

// ---------------- launch ----------------
extern "C" void kernel_launch(void* const* d_in, const int* in_sizes, int n_in,
                              void* d_out, int out_size) {
    (void)in_sizes; (void)n_in; (void)out_size;
    const float* X = (const float*)d_in[0];
    const float* mu_pris = (const float*)d_in[1];
    const float* cov_pris = (const float*)d_in[2];
    float* out = (float*)d_out;

    const size_t smB = (size_t)(102 * 104) * sizeof(float) + (size_t)(96 * 96) * sizeof(__half);
    cudaFuncSetAttribute(feat_kernel, cudaFuncAttributeMaxDynamicSharedMemorySize, (int)smB);

    init_tables_kernel<<<(NTAB + 511) / 512, 512>>>();
    feat_kernel<<<6400, NTHR, smB>>>(X, mu_pris, cov_pris, out);
}

// round 12
// speedup vs baseline: 1.1400x; 1.0105x over previous
#include <cuda_runtime.h>
#include <cuda_fp16.h>
#include <math.h>

#define BATCH 32
#define HW1 960
#define NTAB 9801
#define NTHR 576
#define NW 18

// ---------------- device scratch ----------------
__device__ float g_rg[NTAB];   // AGGD r(gamma) table (monotone increasing)
__device__ float g_feats[BATCH * 100 * 36];
__device__ int g_done[BATCH];  // zero-init; tail CTA resets its slot each launch

static __device__ __forceinline__ float fsqrt_ap(float x) {
    float r; asm("sqrt.approx.f32 %0, %1;" : "=f"(r) : "f"(x)); return r;
}
static __device__ __forceinline__ float fdiv_ap(float a, float b) {
    float r; asm("div.approx.f32 %0, %1, %2;" : "=f"(r) : "f"(a), "f"(b)); return r;
}
static __device__ __forceinline__ unsigned long long pack2(float a, float b) {
    unsigned long long r;
    asm("mov.b64 %0, {%1, %2};" : "=l"(r) : "f"(a), "f"(b));
    return r;
}
static __device__ __forceinline__ void unpack2(unsigned long long p, float& a, float& b) {
    asm("mov.b64 {%0, %1}, %2;" : "=f"(a), "=f"(b) : "l"(p));
}
static __device__ __forceinline__ unsigned long long ffma2(
    unsigned long long a, unsigned long long b, unsigned long long c) {
    unsigned long long d;
    asm("fma.rn.f32x2 %0, %1, %2, %3;" : "=l"(d) : "l"(a), "l"(b), "l"(c));
    return d;
}
// gpu-scope acq_rel add: release prior stores, no L1-flushing sc fence
static __device__ __forceinline__ int atom_add_acqrel(int* p, int v) {
    int old;
    asm volatile("atom.acq_rel.gpu.global.add.s32 %0, [%1], %2;"
                 : "=r"(old) : "l"(p), "r"(v) : "memory");
    return old;
}

// ---------------- per-thread weights ----------------
static __device__ __forceinline__ void make_w7(float* w) {
    const float inv2s2 = 1.0f / (2.0f * (7.0f / 6.0f) * (7.0f / 6.0f));
    float s = 0.f;
#pragma unroll
    for (int j = 0; j < 7; j++) {
        float ax = (float)j - 3.0f;
        w[j] = expf(-ax * ax * inv2s2);
        s += w[j];
    }
    float inv = 1.0f / s;
#pragma unroll
    for (int j = 0; j < 7; j++) w[j] *= inv;
}
static __device__ __forceinline__ void make_w3(float* w) {
    float e = expf(-2.0f);
    float s = 2.f * e + 1.f;
    float inv = 1.0f / s;
    w[0] = e * inv; w[1] = inv; w[2] = e * inv;
}

// ---------------- init: AGGD r(gamma) table ----------------
__global__ void init_tables_kernel() {
    int i = blockIdx.x * blockDim.x + threadIdx.x;
    if (i < NTAB) {
        float g = fmaf((float)i, 0.001f, 0.2f);
        float inv = 1.0f / g;
        g_rg[i] = expf(2.f * lgammaf(2.f * inv) - lgammaf(inv) - lgammaf(3.f * inv));
    }
}

// Warp-cooperative argmin over monotone table; first-index tie-break.
static __device__ __forceinline__ int argmin_table_warp(float t, int lane) {
    int lo = -1, hi = NTAB;
    while (hi - lo > 1) {
        int w = hi - lo - 1;
        int pos = lo + 1 + (int)(((unsigned)lane * (unsigned)w) >> 5);
        float v = __ldg(&g_rg[pos]);
        unsigned m = __ballot_sync(0xffffffffu, v < t);
        if (m == 0u) {
            hi = lo + 1;
        } else {
            int last = 31 - __clz(m);
            int nlo = __shfl_sync(0xffffffffu, pos, last);
            int nhi = hi;
            if (m != 0xffffffffu) {
                int first = __ffs(~m) - 1;
                nhi = __shfl_sync(0xffffffffu, pos, first);
            }
            lo = nlo; hi = nhi;
        }
    }
    int j = hi;
    if (j <= 0) return 0;
    if (j >= NTAB) return NTAB - 1;
    float d0 = fabsf(__ldg(&g_rg[j - 1]) - t);
    float d1 = fabsf(__ldg(&g_rg[j]) - t);
    return (d0 <= d1) ? (j - 1) : j;
}

// ---------------- AGGD stats: half2 pair loads, predicated counts ----------------
// xnb: fp16 BSxBS block (row stride BS halves, 4-byte aligned rows).
// Each lane owns a column pair; 5 LDS per 2 elements; no shuffles in the hot loop.
template <int BS>
static __device__ __forceinline__ void aggd_features(
    const __half* xnb, float Nf, int b, int blk, int foff,
    int tid, float (*s_wsum)[20], float* s_tot, float* s_par) {
    constexpr int H2 = BS / 2;                 // pairs per row: 48 / 24
    constexpr int NCH = (H2 + 31) / 32;        // pair chunks: 2 / 1
    int warp = tid >> 5, lane = tid & 31;

    float accf[15];
#pragma unroll
    for (int k = 0; k < 15; k++) accf[k] = 0.f;
    float cnt[5];
#pragma unroll
    for (int k = 0; k < 5; k++) cnt[k] = 0.f;

    for (int r = warp; r < BS; r += NW) {
        int rm = (r == 0) ? (BS - 1) : (r - 1);
        const __half* rowC = xnb + r * BS;
        const __half* rowM = xnb + rm * BS;
#pragma unroll
        for (int k = 0; k < NCH; k++) {
            int p = k * 32 + lane;
            bool act = ((H2 % 32) == 0) || (p < H2);
            int ps = act ? p : 0;
            int c0 = 2 * ps;
            int cmi = (ps == 0) ? (BS - 1) : (c0 - 1);
            int cpi = (ps == H2 - 1) ? 0 : (c0 + 2);
            float2 fC = __half22float2(*(const half2*)(rowC + c0));
            float2 fM = __half22float2(*(const half2*)(rowM + c0));
            float cmC = __half2float(rowC[cmi]);
            float cmM = __half2float(rowM[cmi]);
            float cpM = __half2float(rowM[cpi]);
            if (!act) { fC.x = 0.f; fC.y = 0.f; }  // x factor=0 -> zero contributions
            // element c0
            {
                float x0 = fC.x;
                float ys[5];
                ys[0] = x0;
                ys[1] = x0 * cmC;   // shift (0,1)
                ys[2] = x0 * fM.x;  // shift (1,0)
                ys[3] = x0 * cmM;   // shift (1,1)
                ys[4] = x0 * fM.y;  // shift (1,-1)
#pragma unroll
                for (int s = 0; s < 5; s++) {
                    float v = ys[s], fa = fabsf(v);
                    accf[s * 3 + 0] = fmaf(v, v, accf[s * 3 + 0]);
                    accf[s * 3 + 1] = fmaf(v, fa, accf[s * 3 + 1]);
                    accf[s * 3 + 2] += fa;
                    if (v > 0.f) cnt[s] += 1.f;
                }
            }
            // element c0+1
            {
                float x1 = fC.y;
                float ys[5];
                ys[0] = x1;
                ys[1] = x1 * fC.x;
                ys[2] = x1 * fM.y;
                ys[3] = x1 * fM.x;
                ys[4] = x1 * cpM;
#pragma unroll
                for (int s = 0; s < 5; s++) {
                    float v = ys[s], fa = fabsf(v);
                    accf[s * 3 + 0] = fmaf(v, v, accf[s * 3 + 0]);
                    accf[s * 3 + 1] = fmaf(v, fa, accf[s * 3 + 1]);
                    accf[s * 3 + 2] += fa;
                    if (v > 0.f) cnt[s] += 1.f;
                }
            }
        }
    }
#pragma unroll
    for (int k = 0; k < 15; k++)
#pragma unroll
        for (int off = 16; off > 0; off >>= 1)
            accf[k] += __shfl_down_sync(0xffffffffu, accf[k], off);
#pragma unroll
    for (int k = 0; k < 5; k++)
#pragma unroll
        for (int off = 16; off > 0; off >>= 1)
            cnt[k] += __shfl_down_sync(0xffffffffu, cnt[k], off);
    if (lane == 0) {
#pragma unroll
        for (int k = 0; k < 15; k++) s_wsum[warp][k] = accf[k];
#pragma unroll
        for (int s = 0; s < 5; s++) s_wsum[warp][15 + s] = cnt[s];
    }
    __syncthreads();
    if (tid < 20) {
        float s = 0.f;
        for (int wi = 0; wi < NW; wi++) s += s_wsum[wi][tid];
        s_tot[tid] = s;
    }
    __syncthreads();
    if (tid < 5) {
        float S2 = s_tot[tid * 3 + 0], SV = s_tot[tid * 3 + 1], SA = s_tot[tid * 3 + 2];
        float CP = s_tot[15 + tid];
        float SP2 = 0.5f * (S2 + SV);
        float SN2 = fmaxf(0.5f * (S2 - SV), 0.f);
        float CN = Nf - CP;
        float lstd = sqrtf(SN2 / fmaxf(CN, 1.f));
        float rstd = sqrtf(SP2 / fmaxf(CP, 1.f));
        s_par[5 + tid] = lstd;
        s_par[10 + tid] = rstd;
        float gh = lstd / fmaxf(rstd, 1e-12f);
        float ma = SA / Nf, ms = S2 / Nf;
        float rhat = (ma * ma) / fmaxf(ms, 1e-12f);
        float gh2 = gh * gh;
        s_par[tid] = rhat * (gh2 * gh + 1.f) * (gh + 1.f) / ((gh2 + 1.f) * (gh2 + 1.f));
    }
    __syncthreads();
    if (warp < 5) {
        int idxm = argmin_table_warp(s_par[warp], lane);
        if (lane == 0) {
            float alpha = (float)(0.2 + 0.001 * (double)idxm);
            float conv = expf(0.5f * (lgammaf(1.f / alpha) - lgammaf(3.f / alpha)));
            float bl = s_par[5 + warp] * conv, br = s_par[10 + warp] * conv;
            float* fo = &g_feats[((size_t)b * 100 + blk) * 36 + foff];
            if (warp == 0) {
                fo[0] = alpha;
                fo[1] = 0.5f * (bl + br);
            } else {
                int o = 2 + (warp - 1) * 4;
                fo[o] = alpha;
                fo[o + 1] = (br - bl) * expf(lgammaf(2.f / alpha) - lgammaf(1.f / alpha));
                fo[o + 2] = bl;
                fo[o + 3] = br;
            }
            // no __threadfence here: the tail-trigger atomic carries release semantics
        }
    }
}

// ---------------- unified feature kernel with fused per-image finalization -----
__global__ __launch_bounds__(NTHR, 3) void feat_kernel(
    const float* __restrict__ X, const float* __restrict__ mu_pris,
    const float* __restrict__ cov_pris, float* __restrict__ out) {
    extern __shared__ float sm[];
    __shared__ float s_wsum[NW][20];
    __shared__ float s_tot[20];
    __shared__ float s_par[15];
    __shared__ int s_tail;
    int tid = threadIdx.x, warp = tid >> 5, lane = tid & 31;
    int id = blockIdx.x;
    int b;

    if (id < 3200) {
        // -------- scale 1: 96x96 --------
        b = id / 100;
        int blk = id - 100 * b;
        int by0 = (blk / 10) * 96, bx0 = (blk % 10) * 96;
        const int TS = 104;
        float* T = sm;                          // 102 x 104
        __half* xn = (__half*)(sm + 102 * TS);  // 96 x 96 fp16
        const float* im = X + (size_t)b * HW1 * HW1;

        if (bx0 != 0 && bx0 != 864) {
            int astart = bx0 - 4;
            for (int r = warp; r < 102; r += NW) {
                int gy = by0 + r - 3; gy = gy < 0 ? 0 : (gy > 959 ? 959 : gy);
                const float4* rowp = (const float4*)(im + (size_t)gy * HW1 + astart);
                if (lane < 26) {
                    float4 v = __ldg(rowp + lane);
                    *(float4*)&T[r * TS + 4 * lane] = v;
                }
            }
        } else {
            for (int r = warp; r < 102; r += NW) {
                int gy = by0 + r - 3; gy = gy < 0 ? 0 : (gy > 959 ? 959 : gy);
                const float* rowp = im + (size_t)gy * HW1;
#pragma unroll
                for (int k = 0; k < 4; k++) {
                    int c = lane + 32 * k;
                    if (k < 3 || c < 102) {
                        int gx = bx0 + c - 3; gx = gx < 0 ? 0 : (gx > 959 ? 959 : gx);
                        T[r * TS + c + 1] = __ldg(rowp + gx);
                    }
                }
            }
        }
        float w7[7]; make_w7(w7);
        unsigned long long wp[7];
#pragma unroll
        for (int t = 0; t < 7; t++) wp[t] = pack2(w7[t], w7[t]);
        __syncthreads();

        int seg = warp / 3, strip = warp - seg * 3;
        int c = strip * 32 + lane;
        int r0 = seg * 16;
        unsigned long long ring[7];
#pragma unroll
        for (int j = 0; j < 22; j++) {
            const float* row = &T[(r0 + j) * TS + c + 1];
            unsigned long long acc = 0ull;
#pragma unroll
            for (int t = 0; t < 7; t++) {
                float v = row[t];
                acc = ffma2(wp[t], pack2(v, v * v), acc);
            }
            ring[j % 7] = acc;
            if (j >= 6) {
                unsigned long long me = 0ull;
#pragma unroll
                for (int i = 0; i < 7; i++) me = ffma2(wp[i], ring[(j - 6 + i) % 7], me);
                float mu, e2; unpack2(me, mu, e2);
                float var = fmaxf(fabsf(e2 - mu * mu), 1e-30f);
                float sig = fsqrt_ap(var);
                int rloc = r0 + j - 6;
                float x = T[(rloc + 3) * TS + (c + 4)];
                xn[rloc * 96 + c] = __float2half(fdiv_ap(x - mu, sig + 1.f));
            }
        }
        __syncthreads();
        aggd_features<96>(xn, 9216.f, b, blk, 0, tid, s_wsum, s_tot, s_par);
    } else {
        // -------- scale 2: fused downsample + 48x48, xn stored fp16 --------
        int id2 = id - 3200;
        b = id2 / 100;
        int blk = id2 - 100 * b;
        int by0 = (blk / 10) * 48, bx0 = (blk % 10) * 48;
        float* Dh = sm;                    // 109 x 54 (reused as xnH after vert conv)
        float* T2 = Dh + 109 * 54;         // 54 x 54 downsampled tile
        float* rX = T2 + 54 * 54;          // 54 x 48
        float* rX2 = rX + 54 * 48;         // 54 x 48
        __half* xnH = (__half*)Dh;         // 48 x 48 fp16 (alias of dead Dh region)
        const float* im = X + (size_t)b * HW1 * HW1;
        float w[7]; make_w7(w);
        float w3v[3]; make_w3(w3v);
        float w3a = w3v[0], w3b = w3v[1], w3c = w3v[2];
        int rbase = 2 * by0 - 7;

        if (bx0 != 0 && bx0 != 432) {
            int astart2 = 2 * bx0 - 8;
            for (int i = warp; i < 109; i += NW) {
                int ri = rbase + i;
                if (ri >= 0 && ri < 960) {
                    float4 v = make_float4(0.f, 0.f, 0.f, 0.f);
                    if (lane < 28)
                        v = __ldg((const float4*)(im + (size_t)ri * HW1 + astart2) + lane);
                    float nx = __shfl_down_sync(0xffffffffu, v.x, 1);
                    float ny = __shfl_down_sync(0xffffffffu, v.y, 1);
                    if (lane < 27) {
                        float o0 = fmaf(w3a, v.y, fmaf(w3b, v.z, w3c * v.w));
                        float o1 = fmaf(w3a, v.w, fmaf(w3b, nx, w3c * ny));
                        *(float2*)&Dh[i * 54 + 2 * lane] = make_float2(o0, o1);
                    }
                } else {
                    for (int k2 = lane; k2 < 54; k2 += 32) Dh[i * 54 + k2] = 0.f;
                }
            }
        } else {
            for (int idx = tid; idx < 109 * 54; idx += NTHR) {
                int i = idx / 54, cc = idx - 54 * i;
                int ri = rbase + i;
                float s = 0.f;
                if (ri >= 0 && ri < 960) {
                    int gxc = bx0 + cc - 3; gxc = gxc < 0 ? 0 : (gxc > 479 ? 479 : gxc);
                    int sx = 2 * gxc - 1;
                    const float* rp = &im[(size_t)ri * HW1];
                    if (sx >= 0) s = fmaf(w3a, __ldg(&rp[sx]), s);
                    s = fmaf(w3b, __ldg(&rp[sx + 1]), s);
                    if (sx + 2 < 960) s = fmaf(w3c, __ldg(&rp[sx + 2]), s);
                }
                Dh[idx] = s;
            }
        }
        __syncthreads();
        for (int idx = tid; idx < 54 * 54; idx += NTHR) {
            int r = idx / 54, cc = idx - 54 * r;
            int gyc = by0 + r - 3; gyc = gyc < 0 ? 0 : (gyc > 479 ? 479 : gyc);
            int row0 = 2 * (gyc - by0) + 6;
            const float* p = &Dh[row0 * 54 + cc];
            T2[idx] = fmaf(w3a, p[0], fmaf(w3b, p[54], w3c * p[108]));
        }
        __syncthreads();
        for (int idx = tid; idx < 54 * 48; idx += NTHR) {
            int r = idx / 48, cc = idx - 48 * r;
            const float* tr = &T2[r * 54 + cc];
            float a1 = 0.f, a2 = 0.f;
#pragma unroll
            for (int t = 0; t < 7; t++) {
                float v = tr[t];
                a1 = fmaf(w[t], v, a1);
                a2 = fmaf(w[t], v * v, a2);
            }
            rX[idx] = a1; rX2[idx] = a2;
        }
        __syncthreads();  // Dh no longer needed; safe to overwrite as xnH below
        for (int idx = tid; idx < 48 * 48; idx += NTHR) {
            int r = idx / 48, cc = idx - 48 * r;
            float mu = 0.f, e2 = 0.f;
#pragma unroll
            for (int i = 0; i < 7; i++) {
                mu = fmaf(w[i], rX[(r + i) * 48 + cc], mu);
                e2 = fmaf(w[i], rX2[(r + i) * 48 + cc], e2);
            }
            float var = fmaxf(fabsf(e2 - mu * mu), 1e-30f);
            float sig = fsqrt_ap(var);
            float x = T2[(r + 3) * 54 + cc + 3];
            xnH[r * 48 + cc] = __float2half(fdiv_ap(x - mu, sig + 1.f));
        }
        __syncthreads();
        aggd_features<48>(xnH, 2304.f, b, blk, 18, tid, s_wsum, s_tot, s_par);
    }

    // -------- fused finalization: last CTA of image b does cov + Cholesky --------
    __syncthreads();  // intra-CTA: all feature stores ordered before the atomic below
    if (tid == 0) s_tail = (atom_add_acqrel(&g_done[b], 1) == 199) ? 1 : 0;
    __syncthreads();
    if (s_tail) {
        if (tid == 0) g_done[b] = 0;  // reset slot for next graph replay
        float* sd = sm;               // 3600
        float* sM = sm + 3600;        // 36*37
        float* smu = sm + 3600 + 36 * 37;
        float* sdiff = smu + 36;
        float* sz = sdiff + 36;
        const float* fb = &g_feats[(size_t)b * 3600];
        for (int i = tid; i < 3600; i += NTHR) sd[i] = __ldcg(&fb[i]);
        __syncthreads();
        if (tid < 36) {
            float s = 0.f;
            for (int n = 0; n < 100; n++) s += sd[n * 36 + tid];
            float m = s / 100.0f;
            smu[tid] = m;
            sdiff[tid] = mu_pris[tid] - m;
        }
        __syncthreads();
        for (int idx = tid; idx < 1296; idx += NTHR) {
            int f = idx / 36, g = idx - f * 36;
            if (g < f) continue;
            float mf = smu[f], mg = smu[g];
            float a0 = 0.f, a1 = 0.f, a2 = 0.f, a3 = 0.f;
            for (int n = 0; n < 100; n += 4) {
                a0 = fmaf(sd[n * 36 + f] - mf, sd[n * 36 + g] - mg, a0);
                a1 = fmaf(sd[(n + 1) * 36 + f] - mf, sd[(n + 1) * 36 + g] - mg, a1);
                a2 = fmaf(sd[(n + 2) * 36 + f] - mf, sd[(n + 2) * 36 + g] - mg, a2);
                a3 = fmaf(sd[(n + 3) * 36 + f] - mf, sd[(n + 3) * 36 + g] - mg, a3);
            }
            float s = ((a0 + a1) + (a2 + a3)) / 99.0f;
            float m = 0.5f * (cov_pris[idx] + s);
            sM[f * 37 + g] = m;
            sM[g * 37 + f] = m;
        }
        __syncthreads();
        if (tid < 32) {
            for (int j = 0; j < 36; j++) {
                float pd = 0.f, pz = 0.f;
                for (int k = lane; k < j; k += 32) {
                    float l = sM[j * 37 + k];
                    pd = fmaf(l, l, pd);
                    pz = fmaf(l, sz[k], pz);
                }
#pragma unroll
                for (int off = 16; off > 0; off >>= 1) {
                    pd += __shfl_down_sync(0xffffffffu, pd, off);
                    pz += __shfl_down_sync(0xffffffffu, pz, off);
                }
                if (lane == 0) {
                    float d = sqrtf(fmaxf(sM[j * 37 + j] - pd, 1e-20f));
                    sM[j * 37 + j] = d;
                    sz[j] = (sdiff[j] - pz) / d;
                }
                __syncwarp();
                float dj = sM[j * 37 + j];
                for (int i = j + 1 + lane; i < 36; i += 32) {
                    float s = sM[i * 37 + j];
                    for (int k = 0; k < j; k++) s -= sM[i * 37 + k] * sM[j * 37 + k];
                    sM[i * 37 + j] = s / dj;
                }
                __syncwarp();
            }
            if (lane == 0) {
                float q = 0.f;
                for (int i = 0; i < 36; i++) q += sz[i] * sz[i];
                out[b] = sqrtf(fmaxf(q, 0.f));
            }
        }
    }
}

// ---------------- launch ----------------
extern "C" void kernel_launch(void* const* d_in, const int* in_sizes, int n_in,
                              void* d_out, int out_size) {
    (void)in_sizes; (void)n_in; (void)out_size;
    const float* X = (const float*)d_in[0];
    const float* mu_pris = (const float*)d_in[1];
    const float* cov_pris = (const float*)d_in[2];
    float* out = (float*)d_out;

    const size_t smB = (size_t)(102 * 104) * sizeof(float) + (size_t)(96 * 96) * sizeof(__half);
    cudaFuncSetAttribute(feat_kernel, cudaFuncAttributeMaxDynamicSharedMemorySize, (int)smB);

    init_tables_kernel<<<(NTAB + 511) / 512, 512>>>();
    feat_kernel<<<6400, NTHR, smB>>>(X, mu_pris, cov_pris, out);
}

// round 13
// speedup vs baseline: 1.1454x; 1.0048x over previous
#include <cuda_runtime.h>
#include <cuda_fp16.h>
#include <math.h>

#define BATCH 32
#define HW1 960
#define NTAB 9801
#define NTHR 576
#define NW 18

// ---------------- device scratch ----------------
__device__ float g_rg[NTAB];   // AGGD r(gamma) table (monotone increasing)
__device__ float g_feats[BATCH * 100 * 36];
__device__ int g_done[BATCH];  // zero-init; tail CTA resets its slot each launch

static __device__ __forceinline__ float fsqrt_ap(float x) {
    float r; asm("sqrt.approx.f32 %0, %1;" : "=f"(r) : "f"(x)); return r;
}
static __device__ __forceinline__ float fdiv_ap(float a, float b) {
    float r; asm("div.approx.f32 %0, %1, %2;" : "=f"(r) : "f"(a), "f"(b)); return r;
}
static __device__ __forceinline__ unsigned long long pack2(float a, float b) {
    unsigned long long r;
    asm("mov.b64 %0, {%1, %2};" : "=l"(r) : "f"(a), "f"(b));
    return r;
}
static __device__ __forceinline__ void unpack2(unsigned long long p, float& a, float& b) {
    asm("mov.b64 {%0, %1}, %2;" : "=f"(a), "=f"(b) : "l"(p));
}
static __device__ __forceinline__ unsigned long long ffma2(
    unsigned long long a, unsigned long long b, unsigned long long c) {
    unsigned long long d;
    asm("fma.rn.f32x2 %0, %1, %2, %3;" : "=l"(d) : "l"(a), "l"(b), "l"(c));
    return d;
}
// release-only gpu-scope add: orders prior stores, does NOT invalidate L1
static __device__ __forceinline__ int atom_add_release(int* p, int v) {
    int old;
    asm volatile("atom.release.gpu.global.add.s32 %0, [%1], %2;"
                 : "=r"(old) : "l"(p), "r"(v) : "memory");
    return old;
}

// ---------------- per-thread weights ----------------
static __device__ __forceinline__ void make_w7(float* w) {
    const float inv2s2 = 1.0f / (2.0f * (7.0f / 6.0f) * (7.0f / 6.0f));
    float s = 0.f;
#pragma unroll
    for (int j = 0; j < 7; j++) {
        float ax = (float)j - 3.0f;
        w[j] = expf(-ax * ax * inv2s2);
        s += w[j];
    }
    float inv = 1.0f / s;
#pragma unroll
    for (int j = 0; j < 7; j++) w[j] *= inv;
}
static __device__ __forceinline__ void make_w3(float* w) {
    float e = expf(-2.0f);
    float s = 2.f * e + 1.f;
    float inv = 1.0f / s;
    w[0] = e * inv; w[1] = inv; w[2] = e * inv;
}

// ---------------- init: AGGD r(gamma) table ----------------
__global__ void init_tables_kernel() {
    int i = blockIdx.x * blockDim.x + threadIdx.x;
    if (i < NTAB) {
        float g = fmaf((float)i, 0.001f, 0.2f);
        float inv = 1.0f / g;
        g_rg[i] = expf(2.f * lgammaf(2.f * inv) - lgammaf(inv) - lgammaf(3.f * inv));
    }
}

// Warp-cooperative argmin over monotone table; first-index tie-break.
static __device__ __forceinline__ int argmin_table_warp(float t, int lane) {
    int lo = -1, hi = NTAB;
    while (hi - lo > 1) {
        int w = hi - lo - 1;
        int pos = lo + 1 + (int)(((unsigned)lane * (unsigned)w) >> 5);
        float v = __ldg(&g_rg[pos]);
        unsigned m = __ballot_sync(0xffffffffu, v < t);
        if (m == 0u) {
            hi = lo + 1;
        } else {
            int last = 31 - __clz(m);
            int nlo = __shfl_sync(0xffffffffu, pos, last);
            int nhi = hi;
            if (m != 0xffffffffu) {
                int first = __ffs(~m) - 1;
                nhi = __shfl_sync(0xffffffffu, pos, first);
            }
            lo = nlo; hi = nhi;
        }
    }
    int j = hi;
    if (j <= 0) return 0;
    if (j >= NTAB) return NTAB - 1;
    float d0 = fabsf(__ldg(&g_rg[j - 1]) - t);
    float d1 = fabsf(__ldg(&g_rg[j]) - t);
    return (d0 <= d1) ? (j - 1) : j;
}

// ---------------- AGGD stats: half2 pair loads, predicated counts ----------------
template <int BS>
static __device__ __forceinline__ void aggd_features(
    const __half* xnb, float Nf, int b, int blk, int foff,
    int tid, float (*s_wsum)[20], float* s_tot, float* s_par) {
    constexpr int H2 = BS / 2;                 // pairs per row: 48 / 24
    constexpr int NCH = (H2 + 31) / 32;        // pair chunks: 2 / 1
    int warp = tid >> 5, lane = tid & 31;

    float accf[15];
#pragma unroll
    for (int k = 0; k < 15; k++) accf[k] = 0.f;
    float cnt[5];
#pragma unroll
    for (int k = 0; k < 5; k++) cnt[k] = 0.f;

    for (int r = warp; r < BS; r += NW) {
        int rm = (r == 0) ? (BS - 1) : (r - 1);
        const __half* rowC = xnb + r * BS;
        const __half* rowM = xnb + rm * BS;
#pragma unroll
        for (int k = 0; k < NCH; k++) {
            int p = k * 32 + lane;
            bool act = ((H2 % 32) == 0) || (p < H2);
            int ps = act ? p : 0;
            int c0 = 2 * ps;
            int cmi = (ps == 0) ? (BS - 1) : (c0 - 1);
            int cpi = (ps == H2 - 1) ? 0 : (c0 + 2);
            float2 fC = __half22float2(*(const half2*)(rowC + c0));
            float2 fM = __half22float2(*(const half2*)(rowM + c0));
            float cmC = __half2float(rowC[cmi]);
            float cmM = __half2float(rowM[cmi]);
            float cpM = __half2float(rowM[cpi]);
            if (!act) { fC.x = 0.f; fC.y = 0.f; }
            {
                float x0 = fC.x;
                float ys[5];
                ys[0] = x0;
                ys[1] = x0 * cmC;
                ys[2] = x0 * fM.x;
                ys[3] = x0 * cmM;
                ys[4] = x0 * fM.y;
#pragma unroll
                for (int s = 0; s < 5; s++) {
                    float v = ys[s], fa = fabsf(v);
                    accf[s * 3 + 0] = fmaf(v, v, accf[s * 3 + 0]);
                    accf[s * 3 + 1] = fmaf(v, fa, accf[s * 3 + 1]);
                    accf[s * 3 + 2] += fa;
                    if (v > 0.f) cnt[s] += 1.f;
                }
            }
            {
                float x1 = fC.y;
                float ys[5];
                ys[0] = x1;
                ys[1] = x1 * fC.x;
                ys[2] = x1 * fM.y;
                ys[3] = x1 * fM.x;
                ys[4] = x1 * cpM;
#pragma unroll
                for (int s = 0; s < 5; s++) {
                    float v = ys[s], fa = fabsf(v);
                    accf[s * 3 + 0] = fmaf(v, v, accf[s * 3 + 0]);
                    accf[s * 3 + 1] = fmaf(v, fa, accf[s * 3 + 1]);
                    accf[s * 3 + 2] += fa;
                    if (v > 0.f) cnt[s] += 1.f;
                }
            }
        }
    }
#pragma unroll
    for (int k = 0; k < 15; k++)
#pragma unroll
        for (int off = 16; off > 0; off >>= 1)
            accf[k] += __shfl_down_sync(0xffffffffu, accf[k], off);
#pragma unroll
    for (int k = 0; k < 5; k++)
#pragma unroll
        for (int off = 16; off > 0; off >>= 1)
            cnt[k] += __shfl_down_sync(0xffffffffu, cnt[k], off);
    if (lane == 0) {
#pragma unroll
        for (int k = 0; k < 15; k++) s_wsum[warp][k] = accf[k];
#pragma unroll
        for (int s = 0; s < 5; s++) s_wsum[warp][15 + s] = cnt[s];
    }
    __syncthreads();
    if (tid < 20) {
        float s = 0.f;
        for (int wi = 0; wi < NW; wi++) s += s_wsum[wi][tid];
        s_tot[tid] = s;
    }
    __syncthreads();
    if (tid < 5) {
        float S2 = s_tot[tid * 3 + 0], SV = s_tot[tid * 3 + 1], SA = s_tot[tid * 3 + 2];
        float CP = s_tot[15 + tid];
        float SP2 = 0.5f * (S2 + SV);
        float SN2 = fmaxf(0.5f * (S2 - SV), 0.f);
        float CN = Nf - CP;
        float lstd = sqrtf(SN2 / fmaxf(CN, 1.f));
        float rstd = sqrtf(SP2 / fmaxf(CP, 1.f));
        s_par[5 + tid] = lstd;
        s_par[10 + tid] = rstd;
        float gh = lstd / fmaxf(rstd, 1e-12f);
        float ma = SA / Nf, ms = S2 / Nf;
        float rhat = (ma * ma) / fmaxf(ms, 1e-12f);
        float gh2 = gh * gh;
        s_par[tid] = rhat * (gh2 * gh + 1.f) * (gh + 1.f) / ((gh2 + 1.f) * (gh2 + 1.f));
    }
    __syncthreads();
    if (warp < 5) {
        int idxm = argmin_table_warp(s_par[warp], lane);
        if (lane == 0) {
            float alpha = (float)(0.2 + 0.001 * (double)idxm);
            float conv = expf(0.5f * (lgammaf(1.f / alpha) - lgammaf(3.f / alpha)));
            float bl = s_par[5 + warp] * conv, br = s_par[10 + warp] * conv;
            float* fo = &g_feats[((size_t)b * 100 + blk) * 36 + foff];
            if (warp == 0) {
                fo[0] = alpha;
                fo[1] = 0.5f * (bl + br);
            } else {
                int o = 2 + (warp - 1) * 4;
                fo[o] = alpha;
                fo[o + 1] = (br - bl) * expf(lgammaf(2.f / alpha) - lgammaf(1.f / alpha));
                fo[o + 2] = bl;
                fo[o + 3] = br;
            }
            // ordering provided by the release atomic below; no fence here
        }
    }
}

// ---------------- unified feature kernel with fused per-image finalization -----
__global__ __launch_bounds__(NTHR, 3) void feat_kernel(
    const float* __restrict__ X, const float* __restrict__ mu_pris,
    const float* __restrict__ cov_pris, float* __restrict__ out) {
    extern __shared__ float sm[];
    __shared__ float s_wsum[NW][20];
    __shared__ float s_tot[20];
    __shared__ float s_par[15];
    __shared__ int s_tail;
    int tid = threadIdx.x, warp = tid >> 5, lane = tid & 31;
    int id = blockIdx.x;
    int b;

    if (id < 3200) {
        // -------- scale 1: 96x96 --------
        b = id / 100;
        int blk = id - 100 * b;
        int by0 = (blk / 10) * 96, bx0 = (blk % 10) * 96;
        const int TS = 104;
        float* T = sm;                          // 102 x 104
        __half* xn = (__half*)(sm + 102 * TS);  // 96 x 96 fp16
        const float* im = X + (size_t)b * HW1 * HW1;

        if (bx0 != 0 && bx0 != 864) {
            int astart = bx0 - 4;
            for (int r = warp; r < 102; r += NW) {
                int gy = by0 + r - 3; gy = gy < 0 ? 0 : (gy > 959 ? 959 : gy);
                const float4* rowp = (const float4*)(im + (size_t)gy * HW1 + astart);
                if (lane < 26) {
                    float4 v = __ldg(rowp + lane);
                    *(float4*)&T[r * TS + 4 * lane] = v;
                }
            }
        } else {
            for (int r = warp; r < 102; r += NW) {
                int gy = by0 + r - 3; gy = gy < 0 ? 0 : (gy > 959 ? 959 : gy);
                const float* rowp = im + (size_t)gy * HW1;
#pragma unroll
                for (int k = 0; k < 4; k++) {
                    int c = lane + 32 * k;
                    if (k < 3 || c < 102) {
                        int gx = bx0 + c - 3; gx = gx < 0 ? 0 : (gx > 959 ? 959 : gx);
                        T[r * TS + c + 1] = __ldg(rowp + gx);
                    }
                }
            }
        }
        float w7[7]; make_w7(w7);
        unsigned long long wp[7];
#pragma unroll
        for (int t = 0; t < 7; t++) wp[t] = pack2(w7[t], w7[t]);
        __syncthreads();

        int seg = warp / 3, strip = warp - seg * 3;
        int c = strip * 32 + lane;
        int r0 = seg * 16;
        unsigned long long ring[7];
#pragma unroll
        for (int j = 0; j < 22; j++) {
            const float* row = &T[(r0 + j) * TS + c + 1];
            unsigned long long acc = 0ull;
#pragma unroll
            for (int t = 0; t < 7; t++) {
                float v = row[t];
                acc = ffma2(wp[t], pack2(v, v * v), acc);
            }
            ring[j % 7] = acc;
            if (j >= 6) {
                unsigned long long me = 0ull;
#pragma unroll
                for (int i = 0; i < 7; i++) me = ffma2(wp[i], ring[(j - 6 + i) % 7], me);
                float mu, e2; unpack2(me, mu, e2);
                float var = fmaxf(fabsf(e2 - mu * mu), 1e-30f);
                float sig = fsqrt_ap(var);
                int rloc = r0 + j - 6;
                float x = T[(rloc + 3) * TS + (c + 4)];
                xn[rloc * 96 + c] = __float2half(fdiv_ap(x - mu, sig + 1.f));
            }
        }
        __syncthreads();
        aggd_features<96>(xn, 9216.f, b, blk, 0, tid, s_wsum, s_tot, s_par);
    } else {
        // -------- scale 2: fused downsample + 48x48, xn stored fp16 --------
        int id2 = id - 3200;
        b = id2 / 100;
        int blk = id2 - 100 * b;
        int by0 = (blk / 10) * 48, bx0 = (blk % 10) * 48;
        float* Dh = sm;                    // 109 x 54 (reused as xnH after vert conv)
        float* T2 = Dh + 109 * 54;         // 54 x 54 downsampled tile
        unsigned long long* rXp =          // 54 x 48 packed (mu, e2) row-convs
            (unsigned long long*)(T2 + 54 * 54);
        __half* xnH = (__half*)Dh;         // 48 x 48 fp16 (alias of dead Dh region)
        const float* im = X + (size_t)b * HW1 * HW1;
        float w[7]; make_w7(w);
        unsigned long long wp[7];
#pragma unroll
        for (int t = 0; t < 7; t++) wp[t] = pack2(w[t], w[t]);
        float w3v[3]; make_w3(w3v);
        float w3a = w3v[0], w3b = w3v[1], w3c = w3v[2];
        int rbase = 2 * by0 - 7;

        if (bx0 != 0 && bx0 != 432) {
            int astart2 = 2 * bx0 - 8;
            for (int i = warp; i < 109; i += NW) {
                int ri = rbase + i;
                if (ri >= 0 && ri < 960) {
                    float4 v = make_float4(0.f, 0.f, 0.f, 0.f);
                    if (lane < 28)
                        v = __ldg((const float4*)(im + (size_t)ri * HW1 + astart2) + lane);
                    float nx = __shfl_down_sync(0xffffffffu, v.x, 1);
                    float ny = __shfl_down_sync(0xffffffffu, v.y, 1);
                    if (lane < 27) {
                        float o0 = fmaf(w3a, v.y, fmaf(w3b, v.z, w3c * v.w));
                        float o1 = fmaf(w3a, v.w, fmaf(w3b, nx, w3c * ny));
                        *(float2*)&Dh[i * 54 + 2 * lane] = make_float2(o0, o1);
                    }
                } else {
                    for (int k2 = lane; k2 < 54; k2 += 32) Dh[i * 54 + k2] = 0.f;
                }
            }
        } else {
            for (int idx = tid; idx < 109 * 54; idx += NTHR) {
                int i = idx / 54, cc = idx - 54 * i;
                int ri = rbase + i;
                float s = 0.f;
                if (ri >= 0 && ri < 960) {
                    int gxc = bx0 + cc - 3; gxc = gxc < 0 ? 0 : (gxc > 479 ? 479 : gxc);
                    int sx = 2 * gxc - 1;
                    const float* rp = &im[(size_t)ri * HW1];
                    if (sx >= 0) s = fmaf(w3a, __ldg(&rp[sx]), s);
                    s = fmaf(w3b, __ldg(&rp[sx + 1]), s);
                    if (sx + 2 < 960) s = fmaf(w3c, __ldg(&rp[sx + 2]), s);
                }
                Dh[idx] = s;
            }
        }
        __syncthreads();
        for (int idx = tid; idx < 54 * 54; idx += NTHR) {
            int r = idx / 54, cc = idx - 54 * r;
            int gyc = by0 + r - 3; gyc = gyc < 0 ? 0 : (gyc > 479 ? 479 : gyc);
            int row0 = 2 * (gyc - by0) + 6;
            const float* p = &Dh[row0 * 54 + cc];
            T2[idx] = fmaf(w3a, p[0], fmaf(w3b, p[54], w3c * p[108]));
        }
        __syncthreads();
        // MSCN horizontal 7-tap, packed (x, x^2)
        for (int idx = tid; idx < 54 * 48; idx += NTHR) {
            int r = idx / 48, cc = idx - 48 * r;
            const float* tr = &T2[r * 54 + cc];
            unsigned long long acc = 0ull;
#pragma unroll
            for (int t = 0; t < 7; t++) {
                float v = tr[t];
                acc = ffma2(wp[t], pack2(v, v * v), acc);
            }
            rXp[idx] = acc;
        }
        __syncthreads();  // Dh no longer needed; safe to overwrite as xnH below
        // vertical 7-tap packed + normalize, write fp16 xn
        for (int idx = tid; idx < 48 * 48; idx += NTHR) {
            int r = idx / 48, cc = idx - 48 * r;
            unsigned long long me = 0ull;
#pragma unroll
            for (int i = 0; i < 7; i++)
                me = ffma2(wp[i], rXp[(r + i) * 48 + cc], me);
            float mu, e2; unpack2(me, mu, e2);
            float var = fmaxf(fabsf(e2 - mu * mu), 1e-30f);
            float sig = fsqrt_ap(var);
            float x = T2[(r + 3) * 54 + cc + 3];
            xnH[r * 48 + cc] = __float2half(fdiv_ap(x - mu, sig + 1.f));
        }
        __syncthreads();
        aggd_features<48>(xnH, 2304.f, b, blk, 18, tid, s_wsum, s_tot, s_par);
    }

    // -------- fused finalization: last CTA of image b does cov + Cholesky --------
    __syncthreads();  // intra-CTA: all feature stores issued before the atomic below
    if (tid == 0) s_tail = (atom_add_release(&g_done[b], 1) == 199) ? 1 : 0;
    __syncthreads();
    if (s_tail) {
        if (tid == 0) {
            int tmp;  // single acquire (tail CTA only) pairs with the 200 releases
            asm volatile("ld.acquire.gpu.global.s32 %0, [%1];"
                         : "=r"(tmp) : "l"(&g_done[b]) : "memory");
            (void)tmp;
            g_done[b] = 0;  // reset slot for next graph replay
        }
        float* sd = sm;               // 3600
        float* sM = sm + 3600;        // 36*37
        float* smu = sm + 3600 + 36 * 37;
        float* sdiff = smu + 36;
        float* sz = sdiff + 36;
        const float* fb = &g_feats[(size_t)b * 3600];
        for (int i = tid; i < 3600; i += NTHR) sd[i] = __ldcg(&fb[i]);
        __syncthreads();
        if (tid < 36) {
            float s = 0.f;
            for (int n = 0; n < 100; n++) s += sd[n * 36 + tid];
            float m = s / 100.0f;
            smu[tid] = m;
            sdiff[tid] = mu_pris[tid] - m;
        }
        __syncthreads();
        for (int idx = tid; idx < 1296; idx += NTHR) {
            int f = idx / 36, g = idx - f * 36;
            if (g < f) continue;
            float mf = smu[f], mg = smu[g];
            float a0 = 0.f, a1 = 0.f, a2 = 0.f, a3 = 0.f;
            for (int n = 0; n < 100; n += 4) {
                a0 = fmaf(sd[n * 36 + f] - mf, sd[n * 36 + g] - mg, a0);
                a1 = fmaf(sd[(n + 1) * 36 + f] - mf, sd[(n + 1) * 36 + g] - mg, a1);
                a2 = fmaf(sd[(n + 2) * 36 + f] - mf, sd[(n + 2) * 36 + g] - mg, a2);
                a3 = fmaf(sd[(n + 3) * 36 + f] - mf, sd[(n + 3) * 36 + g] - mg, a3);
            }
            float s = ((a0 + a1) + (a2 + a3)) / 99.0f;
            float m = 0.5f * (cov_pris[idx] + s);
            sM[f * 37 + g] = m;
            sM[g * 37 + f] = m;
        }
        __syncthreads();
        if (tid < 32) {
            for (int j = 0; j < 36; j++) {
                float pd = 0.f, pz = 0.f;
                for (int k = lane; k < j; k += 32) {
                    float l = sM[j * 37 + k];
                    pd = fmaf(l, l, pd);
                    pz = fmaf(l, sz[k], pz);
                }
#pragma unroll
                for (int off = 16; off > 0; off >>= 1) {
                    pd += __shfl_down_sync(0xffffffffu, pd, off);
                    pz += __shfl_down_sync(0xffffffffu, pz, off);
                }
                if (lane == 0) {
                    float d = sqrtf(fmaxf(sM[j * 37 + j] - pd, 1e-20f));
                    sM[j * 37 + j] = d;
                    sz[j] = (sdiff[j] - pz) / d;
                }
                __syncwarp();
                float dj = sM[j * 37 + j];
                for (int i = j + 1 + lane; i < 36; i += 32) {
                    float s = sM[i * 37 + j];
                    for (int k = 0; k < j; k++) s -= sM[i * 37 + k] * sM[j * 37 + k];
                    sM[i * 37 + j] = s / dj;
                }
                __syncwarp();
            }
            if (lane == 0) {
                float q = 0.f;
                for (int i = 0; i < 36; i++) q += sz[i] * sz[i];
                out[b] = sqrtf(fmaxf(q, 0.f));
            }
        }
    }
}

// ---------------- launch ----------------
extern "C" void kernel_launch(void* const* d_in, const int* in_sizes, int n_in,
                              void* d_out, int out_size) {
    (void)in_sizes; (void)n_in; (void)out_size;
    const float* X = (const float*)d_in[0];
    const float* mu_pris = (const float*)d_in[1];
    const float* cov_pris = (const float*)d_in[2];
    float* out = (float*)d_out;

    const size_t smB = (size_t)(102 * 104) * sizeof(float) + (size_t)(96 * 96) * sizeof(__half);
    cudaFuncSetAttribute(feat_kernel, cudaFuncAttributeMaxDynamicSharedMemorySize, (int)smB);

    init_tables_kernel<<<(NTAB + 511) / 512, 512>>>();
    feat_kernel<<<6400, NTHR, smB>>>(X, mu_pris, cov_pris, out);
}

// round 14
// speedup vs baseline: 1.1459x; 1.0004x over previous
#include <cuda_runtime.h>
#include <cuda_fp16.h>
#include <math.h>

#define BATCH 32
#define HW1 960
#define NTAB 9801
#define NTHR 576
#define NW 18

// ---------------- device scratch ----------------
__device__ float g_rg[NTAB];                 // AGGD r(gamma) table (monotone)
__device__ float g_feats[BATCH * 100 * 36];
__device__ float g_cov[BATCH * 36 * 36];     // (cov_pris + cov_dist)/2 per image

static __device__ __forceinline__ float fsqrt_ap(float x) {
    float r; asm("sqrt.approx.f32 %0, %1;" : "=f"(r) : "f"(x)); return r;
}
static __device__ __forceinline__ float fdiv_ap(float a, float b) {
    float r; asm("div.approx.f32 %0, %1, %2;" : "=f"(r) : "f"(a), "f"(b)); return r;
}
static __device__ __forceinline__ unsigned long long pack2(float a, float b) {
    unsigned long long r;
    asm("mov.b64 %0, {%1, %2};" : "=l"(r) : "f"(a), "f"(b));
    return r;
}
static __device__ __forceinline__ void unpack2(unsigned long long p, float& a, float& b) {
    asm("mov.b64 {%0, %1}, %2;" : "=f"(a), "=f"(b) : "l"(p));
}
static __device__ __forceinline__ unsigned long long ffma2(
    unsigned long long a, unsigned long long b, unsigned long long c) {
    unsigned long long d;
    asm("fma.rn.f32x2 %0, %1, %2, %3;" : "=l"(d) : "l"(a), "l"(b), "l"(c));
    return d;
}

// ---------------- per-thread weights ----------------
static __device__ __forceinline__ void make_w7(float* w) {
    const float inv2s2 = 1.0f / (2.0f * (7.0f / 6.0f) * (7.0f / 6.0f));
    float s = 0.f;
#pragma unroll
    for (int j = 0; j < 7; j++) {
        float ax = (float)j - 3.0f;
        w[j] = expf(-ax * ax * inv2s2);
        s += w[j];
    }
    float inv = 1.0f / s;
#pragma unroll
    for (int j = 0; j < 7; j++) w[j] *= inv;
}
static __device__ __forceinline__ void make_w3(float* w) {
    float e = expf(-2.0f);
    float s = 2.f * e + 1.f;
    float inv = 1.0f / s;
    w[0] = e * inv; w[1] = inv; w[2] = e * inv;
}

// ---------------- init: AGGD r(gamma) table ----------------
__global__ void init_tables_kernel() {
    int i = blockIdx.x * blockDim.x + threadIdx.x;
    if (i < NTAB) {
        float g = fmaf((float)i, 0.001f, 0.2f);
        float inv = 1.0f / g;
        g_rg[i] = expf(2.f * lgammaf(2.f * inv) - lgammaf(inv) - lgammaf(3.f * inv));
    }
}

// Warp-cooperative argmin over monotone table; first-index tie-break.
static __device__ __forceinline__ int argmin_table_warp(float t, int lane) {
    int lo = -1, hi = NTAB;
    while (hi - lo > 1) {
        int w = hi - lo - 1;
        int pos = lo + 1 + (int)(((unsigned)lane * (unsigned)w) >> 5);
        float v = __ldg(&g_rg[pos]);
        unsigned m = __ballot_sync(0xffffffffu, v < t);
        if (m == 0u) {
            hi = lo + 1;
        } else {
            int last = 31 - __clz(m);
            int nlo = __shfl_sync(0xffffffffu, pos, last);
            int nhi = hi;
            if (m != 0xffffffffu) {
                int first = __ffs(~m) - 1;
                nhi = __shfl_sync(0xffffffffu, pos, first);
            }
            lo = nlo; hi = nhi;
        }
    }
    int j = hi;
    if (j <= 0) return 0;
    if (j >= NTAB) return NTAB - 1;
    float d0 = fabsf(__ldg(&g_rg[j - 1]) - t);
    float d1 = fabsf(__ldg(&g_rg[j]) - t);
    return (d0 <= d1) ? (j - 1) : j;
}

// ---------------- AGGD stats: half2 pair loads, predicated counts ----------------
template <int BS>
static __device__ __forceinline__ void aggd_features(
    const __half* xnb, float Nf, int b, int blk, int foff,
    int tid, float (*s_wsum)[20], float* s_tot, float* s_par) {
    constexpr int H2 = BS / 2;                 // pairs per row: 48 / 24
    constexpr int NCH = (H2 + 31) / 32;        // pair chunks: 2 / 1
    int warp = tid >> 5, lane = tid & 31;

    float accf[15];
#pragma unroll
    for (int k = 0; k < 15; k++) accf[k] = 0.f;
    float cnt[5];
#pragma unroll
    for (int k = 0; k < 5; k++) cnt[k] = 0.f;

    for (int r = warp; r < BS; r += NW) {
        int rm = (r == 0) ? (BS - 1) : (r - 1);
        const __half* rowC = xnb + r * BS;
        const __half* rowM = xnb + rm * BS;
#pragma unroll
        for (int k = 0; k < NCH; k++) {
            int p = k * 32 + lane;
            bool act = ((H2 % 32) == 0) || (p < H2);
            int ps = act ? p : 0;
            int c0 = 2 * ps;
            int cmi = (ps == 0) ? (BS - 1) : (c0 - 1);
            int cpi = (ps == H2 - 1) ? 0 : (c0 + 2);
            float2 fC = __half22float2(*(const half2*)(rowC + c0));
            float2 fM = __half22float2(*(const half2*)(rowM + c0));
            float cmC = __half2float(rowC[cmi]);
            float cmM = __half2float(rowM[cmi]);
            float cpM = __half2float(rowM[cpi]);
            if (!act) { fC.x = 0.f; fC.y = 0.f; }
            {
                float x0 = fC.x;
                float ys[5];
                ys[0] = x0;
                ys[1] = x0 * cmC;   // shift (0,1)
                ys[2] = x0 * fM.x;  // shift (1,0)
                ys[3] = x0 * cmM;   // shift (1,1)
                ys[4] = x0 * fM.y;  // shift (1,-1)
#pragma unroll
                for (int s = 0; s < 5; s++) {
                    float v = ys[s], fa = fabsf(v);
                    accf[s * 3 + 0] = fmaf(v, v, accf[s * 3 + 0]);
                    accf[s * 3 + 1] = fmaf(v, fa, accf[s * 3 + 1]);
                    accf[s * 3 + 2] += fa;
                    if (v > 0.f) cnt[s] += 1.f;
                }
            }
            {
                float x1 = fC.y;
                float ys[5];
                ys[0] = x1;
                ys[1] = x1 * fC.x;
                ys[2] = x1 * fM.y;
                ys[3] = x1 * fM.x;
                ys[4] = x1 * cpM;
#pragma unroll
                for (int s = 0; s < 5; s++) {
                    float v = ys[s], fa = fabsf(v);
                    accf[s * 3 + 0] = fmaf(v, v, accf[s * 3 + 0]);
                    accf[s * 3 + 1] = fmaf(v, fa, accf[s * 3 + 1]);
                    accf[s * 3 + 2] += fa;
                    if (v > 0.f) cnt[s] += 1.f;
                }
            }
        }
    }
#pragma unroll
    for (int k = 0; k < 15; k++)
#pragma unroll
        for (int off = 16; off > 0; off >>= 1)
            accf[k] += __shfl_down_sync(0xffffffffu, accf[k], off);
#pragma unroll
    for (int k = 0; k < 5; k++)
#pragma unroll
        for (int off = 16; off > 0; off >>= 1)
            cnt[k] += __shfl_down_sync(0xffffffffu, cnt[k], off);
    if (lane == 0) {
#pragma unroll
        for (int k = 0; k < 15; k++) s_wsum[warp][k] = accf[k];
#pragma unroll
        for (int s = 0; s < 5; s++) s_wsum[warp][15 + s] = cnt[s];
    }
    __syncthreads();
    if (tid < 20) {
        float s = 0.f;
        for (int wi = 0; wi < NW; wi++) s += s_wsum[wi][tid];
        s_tot[tid] = s;
    }
    __syncthreads();
    if (tid < 5) {
        float S2 = s_tot[tid * 3 + 0], SV = s_tot[tid * 3 + 1], SA = s_tot[tid * 3 + 2];
        float CP = s_tot[15 + tid];
        float SP2 = 0.5f * (S2 + SV);
        float SN2 = fmaxf(0.5f * (S2 - SV), 0.f);
        float CN = Nf - CP;
        float lstd = sqrtf(SN2 / fmaxf(CN, 1.f));
        float rstd = sqrtf(SP2 / fmaxf(CP, 1.f));
        s_par[5 + tid] = lstd;
        s_par[10 + tid] = rstd;
        float gh = lstd / fmaxf(rstd, 1e-12f);
        float ma = SA / Nf, ms = S2 / Nf;
        float rhat = (ma * ma) / fmaxf(ms, 1e-12f);
        float gh2 = gh * gh;
        s_par[tid] = rhat * (gh2 * gh + 1.f) * (gh + 1.f) / ((gh2 + 1.f) * (gh2 + 1.f));
    }
    __syncthreads();
    if (warp < 5) {
        int idxm = argmin_table_warp(s_par[warp], lane);
        if (lane == 0) {
            float alpha = (float)(0.2 + 0.001 * (double)idxm);
            float conv = expf(0.5f * (lgammaf(1.f / alpha) - lgammaf(3.f / alpha)));
            float bl = s_par[5 + warp] * conv, br = s_par[10 + warp] * conv;
            float* fo = &g_feats[((size_t)b * 100 + blk) * 36 + foff];
            if (warp == 0) {
                fo[0] = alpha;
                fo[1] = 0.5f * (bl + br);
            } else {
                int o = 2 + (warp - 1) * 4;
                fo[o] = alpha;
                fo[o + 1] = (br - bl) * expf(lgammaf(2.f / alpha) - lgammaf(1.f / alpha));
                fo[o + 2] = bl;
                fo[o + 3] = br;
            }
        }
    }
}

// ---------------- unified feature kernel (split structure, no tail fusion) -----
__global__ __launch_bounds__(NTHR, 3) void feat_kernel(const float* __restrict__ X) {
    extern __shared__ float sm[];
    __shared__ float s_wsum[NW][20];
    __shared__ float s_tot[20];
    __shared__ float s_par[15];
    int tid = threadIdx.x, warp = tid >> 5, lane = tid & 31;
    int id = blockIdx.x;

    if (id < 3200) {
        // -------- scale 1: 96x96 --------
        int b = id / 100;
        int blk = id - 100 * b;
        int by0 = (blk / 10) * 96, bx0 = (blk % 10) * 96;
        const int TS = 104;
        float* T = sm;                          // 102 x 104
        __half* xn = (__half*)(sm + 102 * TS);  // 96 x 96 fp16
        const float* im = X + (size_t)b * HW1 * HW1;

        if (bx0 != 0 && bx0 != 864) {
            int astart = bx0 - 4;
            for (int r = warp; r < 102; r += NW) {
                int gy = by0 + r - 3; gy = gy < 0 ? 0 : (gy > 959 ? 959 : gy);
                const float4* rowp = (const float4*)(im + (size_t)gy * HW1 + astart);
                if (lane < 26) {
                    float4 v = __ldg(rowp + lane);
                    *(float4*)&T[r * TS + 4 * lane] = v;
                }
            }
        } else {
            for (int r = warp; r < 102; r += NW) {
                int gy = by0 + r - 3; gy = gy < 0 ? 0 : (gy > 959 ? 959 : gy);
                const float* rowp = im + (size_t)gy * HW1;
#pragma unroll
                for (int k = 0; k < 4; k++) {
                    int c = lane + 32 * k;
                    if (k < 3 || c < 102) {
                        int gx = bx0 + c - 3; gx = gx < 0 ? 0 : (gx > 959 ? 959 : gx);
                        T[r * TS + c + 1] = __ldg(rowp + gx);
                    }
                }
            }
        }
        float w7[7]; make_w7(w7);
        unsigned long long wp[7];
#pragma unroll
        for (int t = 0; t < 7; t++) wp[t] = pack2(w7[t], w7[t]);
        __syncthreads();

        int seg = warp / 3, strip = warp - seg * 3;
        int c = strip * 32 + lane;
        int r0 = seg * 16;
        unsigned long long ring[7];
#pragma unroll
        for (int j = 0; j < 22; j++) {
            const float* row = &T[(r0 + j) * TS + c + 1];
            unsigned long long acc = 0ull;
#pragma unroll
            for (int t = 0; t < 7; t++) {
                float v = row[t];
                acc = ffma2(wp[t], pack2(v, v * v), acc);
            }
            ring[j % 7] = acc;
            if (j >= 6) {
                unsigned long long me = 0ull;
#pragma unroll
                for (int i = 0; i < 7; i++) me = ffma2(wp[i], ring[(j - 6 + i) % 7], me);
                float mu, e2; unpack2(me, mu, e2);
                float var = fmaxf(fabsf(e2 - mu * mu), 1e-30f);
                float sig = fsqrt_ap(var);
                int rloc = r0 + j - 6;
                float x = T[(rloc + 3) * TS + (c + 4)];
                xn[rloc * 96 + c] = __float2half(fdiv_ap(x - mu, sig + 1.f));
            }
        }
        __syncthreads();
        aggd_features<96>(xn, 9216.f, b, blk, 0, tid, s_wsum, s_tot, s_par);
    } else {
        // -------- scale 2: fused downsample + 48x48, packed conv, fp16 xn --------
        int id2 = id - 3200;
        int b = id2 / 100;
        int blk = id2 - 100 * b;
        int by0 = (blk / 10) * 48, bx0 = (blk % 10) * 48;
        float* Dh = sm;                    // 109 x 54 (later reused as xnH)
        float* T2 = Dh + 109 * 54;         // 54 x 54 downsampled tile
        unsigned long long* rXp =          // 54 x 48 packed (x, x^2) row-convs
            (unsigned long long*)(T2 + 54 * 54);
        __half* xnH = (__half*)Dh;         // 48 x 48 fp16 (alias of dead Dh)
        const float* im = X + (size_t)b * HW1 * HW1;
        float w[7]; make_w7(w);
        unsigned long long wp[7];
#pragma unroll
        for (int t = 0; t < 7; t++) wp[t] = pack2(w[t], w[t]);
        float w3v[3]; make_w3(w3v);
        float w3a = w3v[0], w3b = w3v[1], w3c = w3v[2];
        int rbase = 2 * by0 - 7;

        if (bx0 != 0 && bx0 != 432) {
            int astart2 = 2 * bx0 - 8;
            for (int i = warp; i < 109; i += NW) {
                int ri = rbase + i;
                if (ri >= 0 && ri < 960) {
                    float4 v = make_float4(0.f, 0.f, 0.f, 0.f);
                    if (lane < 28)
                        v = __ldg((const float4*)(im + (size_t)ri * HW1 + astart2) + lane);
                    float nx = __shfl_down_sync(0xffffffffu, v.x, 1);
                    float ny = __shfl_down_sync(0xffffffffu, v.y, 1);
                    if (lane < 27) {
                        float o0 = fmaf(w3a, v.y, fmaf(w3b, v.z, w3c * v.w));
                        float o1 = fmaf(w3a, v.w, fmaf(w3b, nx, w3c * ny));
                        *(float2*)&Dh[i * 54 + 2 * lane] = make_float2(o0, o1);
                    }
                } else {
                    for (int k2 = lane; k2 < 54; k2 += 32) Dh[i * 54 + k2] = 0.f;
                }
            }
        } else {
            for (int idx = tid; idx < 109 * 54; idx += NTHR) {
                int i = idx / 54, cc = idx - 54 * i;
                int ri = rbase + i;
                float s = 0.f;
                if (ri >= 0 && ri < 960) {
                    int gxc = bx0 + cc - 3; gxc = gxc < 0 ? 0 : (gxc > 479 ? 479 : gxc);
                    int sx = 2 * gxc - 1;
                    const float* rp = &im[(size_t)ri * HW1];
                    if (sx >= 0) s = fmaf(w3a, __ldg(&rp[sx]), s);
                    s = fmaf(w3b, __ldg(&rp[sx + 1]), s);
                    if (sx + 2 < 960) s = fmaf(w3c, __ldg(&rp[sx + 2]), s);
                }
                Dh[idx] = s;
            }
        }
        __syncthreads();
        for (int idx = tid; idx < 54 * 54; idx += NTHR) {
            int r = idx / 54, cc = idx - 54 * r;
            int gyc = by0 + r - 3; gyc = gyc < 0 ? 0 : (gyc > 479 ? 479 : gyc);
            int row0 = 2 * (gyc - by0) + 6;
            const float* p = &Dh[row0 * 54 + cc];
            T2[idx] = fmaf(w3a, p[0], fmaf(w3b, p[54], w3c * p[108]));
        }
        __syncthreads();
        for (int idx = tid; idx < 54 * 48; idx += NTHR) {
            int r = idx / 48, cc = idx - 48 * r;
            const float* tr = &T2[r * 54 + cc];
            unsigned long long acc = 0ull;
#pragma unroll
            for (int t = 0; t < 7; t++) {
                float v = tr[t];
                acc = ffma2(wp[t], pack2(v, v * v), acc);
            }
            rXp[idx] = acc;
        }
        __syncthreads();  // Dh dead; safe to overwrite as xnH below
        for (int idx = tid; idx < 48 * 48; idx += NTHR) {
            int r = idx / 48, cc = idx - 48 * r;
            unsigned long long me = 0ull;
#pragma unroll
            for (int i = 0; i < 7; i++)
                me = ffma2(wp[i], rXp[(r + i) * 48 + cc], me);
            float mu, e2; unpack2(me, mu, e2);
            float var = fmaxf(fabsf(e2 - mu * mu), 1e-30f);
            float sig = fsqrt_ap(var);
            float x = T2[(r + 3) * 54 + cc + 3];
            xnH[r * 48 + cc] = __float2half(fdiv_ap(x - mu, sig + 1.f));
        }
        __syncthreads();
        aggd_features<48>(xnH, 2304.f, b, blk, 18, tid, s_wsum, s_tot, s_par);
    }
}

// ---------------- cov: grid (32, 6) — 6 partitions per image --------------------
__global__ __launch_bounds__(256) void cov_kernel(const float* __restrict__ cov_pris) {
    __shared__ float sd[100 * 36];
    __shared__ float smu[36];
    int b = blockIdx.x, part = blockIdx.y, tid = threadIdx.x;
    const int NT = 256;
    const float* fb = &g_feats[(size_t)b * 3600];
    for (int i = tid; i < 3600; i += NT) sd[i] = fb[i];
    __syncthreads();
    if (tid < 36) {
        float s = 0.f;
        for (int n = 0; n < 100; n++) s += sd[n * 36 + tid];
        smu[tid] = s / 100.0f;
    }
    __syncthreads();
    float* gc = &g_cov[(size_t)b * 1296];
    for (int idx = tid; idx < 1296; idx += NT) {
        int f = idx / 36, g = idx - f * 36;
        if (g < f) continue;
        if ((f + g) % 6 != part) continue;  // partition upper triangle 6 ways
        float mf = smu[f], mg = smu[g];
        float a0 = 0.f, a1 = 0.f, a2 = 0.f, a3 = 0.f;
        for (int n = 0; n < 100; n += 4) {
            a0 = fmaf(sd[n * 36 + f] - mf, sd[n * 36 + g] - mg, a0);
            a1 = fmaf(sd[(n + 1) * 36 + f] - mf, sd[(n + 1) * 36 + g] - mg, a1);
            a2 = fmaf(sd[(n + 2) * 36 + f] - mf, sd[(n + 2) * 36 + g] - mg, a2);
            a3 = fmaf(sd[(n + 3) * 36 + f] - mf, sd[(n + 3) * 36 + g] - mg, a3);
        }
        float s = ((a0 + a1) + (a2 + a3)) / 99.0f;
        float m = 0.5f * (cov_pris[idx] + s);
        gc[f * 36 + g] = m;
        gc[g * 36 + f] = m;
    }
}

// ---------------- chol: grid 32 — load cov, warp-0 Cholesky + Mahalanobis ------
__global__ __launch_bounds__(128) void chol_kernel(const float* __restrict__ mu_pris,
                                                   float* __restrict__ out) {
    __shared__ float sM[36 * 37];
    __shared__ float sdiff[36];
    __shared__ float sz[36];
    int b = blockIdx.x, tid = threadIdx.x;
    const float* gc = &g_cov[(size_t)b * 1296];
    for (int i = tid; i < 1296; i += 128) {
        int f = i / 36, g = i - f * 36;
        sM[f * 37 + g] = gc[i];
    }
    if (tid < 36) {
        const float* fb = &g_feats[(size_t)b * 3600];
        float s = 0.f;
        for (int n = 0; n < 100; n++) s += fb[n * 36 + tid];
        sdiff[tid] = mu_pris[tid] - s / 100.0f;
    }
    __syncthreads();
    if (tid < 32) {
        int lane = tid;
        for (int j = 0; j < 36; j++) {
            float pd = 0.f, pz = 0.f;
            for (int k = lane; k < j; k += 32) {
                float l = sM[j * 37 + k];
                pd = fmaf(l, l, pd);
                pz = fmaf(l, sz[k], pz);
            }
#pragma unroll
            for (int off = 16; off > 0; off >>= 1) {
                pd += __shfl_down_sync(0xffffffffu, pd, off);
                pz += __shfl_down_sync(0xffffffffu, pz, off);
            }
            if (lane == 0) {
                float d = sqrtf(fmaxf(sM[j * 37 + j] - pd, 1e-20f));
                sM[j * 37 + j] = d;
                sz[j] = (sdiff[j] - pz) / d;
            }
            __syncwarp();
            float dj = sM[j * 37 + j];
            for (int i = j + 1 + lane; i < 36; i += 32) {
                float s = sM[i * 37 + j];
                for (int k = 0; k < j; k++) s -= sM[i * 37 + k] * sM[j * 37 + k];
                sM[i * 37 + j] = s / dj;
            }
            __syncwarp();
        }
        if (lane == 0) {
            float q = 0.f;
            for (int i = 0; i < 36; i++) q += sz[i] * sz[i];
            out[b] = sqrtf(fmaxf(q, 0.f));
        }
    }
}

// ---------------- launch ----------------
extern "C" void kernel_launch(void* const* d_in, const int* in_sizes, int n_in,
                              void* d_out, int out_size) {
    (void)in_sizes; (void)n_in; (void)out_size;
    const float* X = (const float*)d_in[0];
    const float* mu_pris = (const float*)d_in[1];
    const float* cov_pris = (const float*)d_in[2];
    float* out = (float*)d_out;

    const size_t smB = (size_t)(102 * 104) * sizeof(float) + (size_t)(96 * 96) * sizeof(__half);
    cudaFuncSetAttribute(feat_kernel, cudaFuncAttributeMaxDynamicSharedMemorySize, (int)smB);

    init_tables_kernel<<<(NTAB + 511) / 512, 512>>>();
    feat_kernel<<<6400, NTHR, smB>>>(X);
    cov_kernel<<<dim3(BATCH, 6), 256>>>(cov_pris);
    chol_kernel<<<BATCH, 128>>>(mu_pris, out);
}

// round 15
// speedup vs baseline: 1.2143x; 1.0597x over previous
#include <cuda_runtime.h>
#include <cuda_fp16.h>
#include <math.h>

#define BATCH 32
#define HW1 960
#define NTAB 9801
#define NTHR 576
#define NW 18

// ---------------- device scratch ----------------
__device__ float g_rg[NTAB];   // AGGD r(gamma) table (monotone increasing)
__device__ float g_w7[7];      // 7-tap gaussian, sigma 7/6 (normalized)
__device__ float g_w3[3];      // 3-tap gaussian, sigma 0.5 (normalized, separable)
__device__ float g_feats[BATCH * 100 * 36];

static __device__ __forceinline__ float fsqrt_ap(float x) {
    float r; asm("sqrt.approx.f32 %0, %1;" : "=f"(r) : "f"(x)); return r;
}
static __device__ __forceinline__ float fdiv_ap(float a, float b) {
    float r; asm("div.approx.f32 %0, %1, %2;" : "=f"(r) : "f"(a), "f"(b)); return r;
}
static __device__ __forceinline__ unsigned long long pack2(float a, float b) {
    unsigned long long r;
    asm("mov.b64 %0, {%1, %2};" : "=l"(r) : "f"(a), "f"(b));
    return r;
}
static __device__ __forceinline__ void unpack2(unsigned long long p, float& a, float& b) {
    asm("mov.b64 {%0, %1}, %2;" : "=f"(a), "=f"(b) : "l"(p));
}
static __device__ __forceinline__ unsigned long long ffma2(
    unsigned long long a, unsigned long long b, unsigned long long c) {
    unsigned long long d;
    asm("fma.rn.f32x2 %0, %1, %2, %3;" : "=l"(d) : "l"(a), "l"(b), "l"(c));
    return d;
}

// ---------------- init: table + weights (float; deterministic) ----------------
__global__ void init_tables_kernel() {
    int i = blockIdx.x * blockDim.x + threadIdx.x;
    if (i < NTAB) {
        float g = fmaf((float)i, 0.001f, 0.2f);
        float inv = 1.0f / g;
        g_rg[i] = expf(2.f * lgammaf(2.f * inv) - lgammaf(inv) - lgammaf(3.f * inv));
    }
    if (i == 0) {
        double e[7], s = 0.0, sig = 7.0 / 6.0;
        for (int j = 0; j < 7; j++) {
            double ax = (double)j - 3.0;
            e[j] = exp(-(ax * ax) / (2.0 * sig * sig));
            s += e[j];
        }
        for (int j = 0; j < 7; j++) g_w7[j] = (float)(e[j] / s);
        double e3[3], s3 = 0.0;
        for (int j = 0; j < 3; j++) {
            double ax = (double)j - 1.0;
            e3[j] = exp(-(ax * ax) / 0.5);
            s3 += e3[j];
        }
        for (int j = 0; j < 3; j++) g_w3[j] = (float)(e3[j] / s3);
    }
}

// Warp-cooperative argmin over monotone table; first-index tie-break.
static __device__ __forceinline__ int argmin_table_warp(float t, int lane) {
    int lo = -1, hi = NTAB;
    while (hi - lo > 1) {
        int w = hi - lo - 1;
        int pos = lo + 1 + (int)(((unsigned)lane * (unsigned)w) >> 5);
        float v = __ldg(&g_rg[pos]);
        unsigned m = __ballot_sync(0xffffffffu, v < t);
        if (m == 0u) {
            hi = lo + 1;
        } else {
            int last = 31 - __clz(m);
            int nlo = __shfl_sync(0xffffffffu, pos, last);
            int nhi = hi;
            if (m != 0xffffffffu) {
                int first = __ffs(~m) - 1;
                nhi = __shfl_sync(0xffffffffu, pos, first);
            }
            lo = nlo; hi = nhi;
        }
    }
    int j = hi;
    if (j <= 0) return 0;
    if (j >= NTAB) return NTAB - 1;
    float d0 = fabsf(__ldg(&g_rg[j - 1]) - t);
    float d1 = fabsf(__ldg(&g_rg[j]) - t);
    return (d0 <= d1) ? (j - 1) : j;
}

static __device__ __forceinline__ float to_f32(float v) { return v; }
static __device__ __forceinline__ float to_f32(__half v) { return __half2float(v); }

// ---------------- AGGD stats + features (scalar loads — 296.9us config) ---------
template <int BS, typename TX>
static __device__ __forceinline__ void aggd_features(
    const TX* xnb, int stride, float Nf, int b, int blk, int foff,
    int tid, float (*s_wsum)[20], float* s_tot, float* s_par) {
    int warp = tid >> 5, lane = tid & 31;
    float accf[15];
#pragma unroll
    for (int k = 0; k < 15; k++) accf[k] = 0.f;
    float cnt[5];
#pragma unroll
    for (int k = 0; k < 5; k++) cnt[k] = 0.f;
    for (int r = warp; r < BS; r += NW) {
        int rm = (r == 0) ? (BS - 1) : (r - 1);
        const TX* rowC = xnb + r * stride;
        const TX* rowM = xnb + rm * stride;
#pragma unroll
        for (int c0 = 0; c0 < BS; c0 += 32) {
            int c = c0 + lane;
            bool act = ((BS & 31) == 0) || (c < BS);
            int cs = act ? c : 0;
            int cm = (cs == 0) ? (BS - 1) : (cs - 1);
            int cpn = (cs == BS - 1) ? 0 : (cs + 1);
            float x0 = act ? to_f32(rowC[cs]) : 0.f;
            float y[5];
            y[0] = x0;
            y[1] = x0 * to_f32(rowC[cm]);
            y[2] = x0 * to_f32(rowM[cs]);
            y[3] = x0 * to_f32(rowM[cm]);
            y[4] = x0 * to_f32(rowM[cpn]);
#pragma unroll
            for (int s = 0; s < 5; s++) {
                float v = y[s];
                float fa = fabsf(v);
                accf[s * 3 + 0] = fmaf(v, v, accf[s * 3 + 0]);   // S2
                accf[s * 3 + 1] = fmaf(v, fa, accf[s * 3 + 1]);  // SV
                accf[s * 3 + 2] += fa;                            // SA
                if (v > 0.f) cnt[s] += 1.f;                       // CP
            }
        }
    }
#pragma unroll
    for (int k = 0; k < 15; k++)
#pragma unroll
        for (int off = 16; off > 0; off >>= 1)
            accf[k] += __shfl_down_sync(0xffffffffu, accf[k], off);
#pragma unroll
    for (int k = 0; k < 5; k++)
#pragma unroll
        for (int off = 16; off > 0; off >>= 1)
            cnt[k] += __shfl_down_sync(0xffffffffu, cnt[k], off);
    if (lane == 0) {
#pragma unroll
        for (int k = 0; k < 15; k++) s_wsum[warp][k] = accf[k];
#pragma unroll
        for (int s = 0; s < 5; s++) s_wsum[warp][15 + s] = cnt[s];
    }
    __syncthreads();
    if (tid < 20) {
        float s = 0.f;
        for (int wi = 0; wi < NW; wi++) s += s_wsum[wi][tid];
        s_tot[tid] = s;
    }
    __syncthreads();
    if (tid < 5) {
        float S2 = s_tot[tid * 3 + 0], SV = s_tot[tid * 3 + 1], SA = s_tot[tid * 3 + 2];
        float CP = s_tot[15 + tid];
        float SP2 = 0.5f * (S2 + SV);
        float SN2 = fmaxf(0.5f * (S2 - SV), 0.f);
        float CN = Nf - CP;
        float lstd = sqrtf(SN2 / fmaxf(CN, 1.f));
        float rstd = sqrtf(SP2 / fmaxf(CP, 1.f));
        s_par[5 + tid] = lstd;
        s_par[10 + tid] = rstd;
        float gh = lstd / fmaxf(rstd, 1e-12f);
        float ma = SA / Nf, ms = S2 / Nf;
        float rhat = (ma * ma) / fmaxf(ms, 1e-12f);
        float gh2 = gh * gh;
        s_par[tid] = rhat * (gh2 * gh + 1.f) * (gh + 1.f) / ((gh2 + 1.f) * (gh2 + 1.f));
    }
    __syncthreads();
    if (warp < 5) {
        int idxm = argmin_table_warp(s_par[warp], lane);
        if (lane == 0) {
            float alpha = (float)(0.2 + 0.001 * (double)idxm);
            float conv = expf(0.5f * (lgammaf(1.f / alpha) - lgammaf(3.f / alpha)));
            float bl = s_par[5 + warp] * conv, br = s_par[10 + warp] * conv;
            float* fo = &g_feats[((size_t)b * 100 + blk) * 36 + foff];
            if (warp == 0) {
                fo[0] = alpha;
                fo[1] = 0.5f * (bl + br);
            } else {
                int o = 2 + (warp - 1) * 4;
                fo[o] = alpha;
                fo[o + 1] = (br - bl) * expf(lgammaf(2.f / alpha) - lgammaf(1.f / alpha));
                fo[o + 2] = bl;
                fo[o + 3] = br;
            }
        }
    }
}

// ---------------- unified feature kernel (296.9us config) ------------------------
__global__ __launch_bounds__(NTHR, 3) void feat_kernel(const float* __restrict__ X) {
    extern __shared__ float sm[];
    __shared__ float s_wsum[NW][20];
    __shared__ float s_tot[20];
    __shared__ float s_par[15];
    int tid = threadIdx.x, warp = tid >> 5, lane = tid & 31;
    int id = blockIdx.x;

    if (id < 3200) {
        // -------- scale 1: 96x96 --------
        int b = id / 100, blk = id - 100 * b;
        int by0 = (blk / 10) * 96, bx0 = (blk % 10) * 96;
        const int TS = 104;
        float* T = sm;                          // 102 x 104
        __half* xn = (__half*)(sm + 102 * TS);  // 96 x 96 fp16
        const float* im = X + (size_t)b * HW1 * HW1;

        if (bx0 != 0 && bx0 != 864) {
            int astart = bx0 - 4;
            for (int r = warp; r < 102; r += NW) {
                int gy = by0 + r - 3; gy = gy < 0 ? 0 : (gy > 959 ? 959 : gy);
                const float4* rowp = (const float4*)(im + (size_t)gy * HW1 + astart);
                if (lane < 26) {
                    float4 v = __ldg(rowp + lane);
                    *(float4*)&T[r * TS + 4 * lane] = v;
                }
            }
        } else {
            for (int r = warp; r < 102; r += NW) {
                int gy = by0 + r - 3; gy = gy < 0 ? 0 : (gy > 959 ? 959 : gy);
                const float* rowp = im + (size_t)gy * HW1;
#pragma unroll
                for (int k = 0; k < 4; k++) {
                    int c = lane + 32 * k;
                    if (k < 3 || c < 102) {
                        int gx = bx0 + c - 3; gx = gx < 0 ? 0 : (gx > 959 ? 959 : gx);
                        T[r * TS + c + 1] = __ldg(rowp + gx);
                    }
                }
            }
        }
        float w7l[7];
#pragma unroll
        for (int t = 0; t < 7; t++) w7l[t] = g_w7[t];
        unsigned long long wp[7];
#pragma unroll
        for (int t = 0; t < 7; t++) wp[t] = pack2(w7l[t], w7l[t]);
        __syncthreads();

        int seg = warp / 3, strip = warp - seg * 3;
        int c = strip * 32 + lane;
        int r0 = seg * 16;
        unsigned long long ring[7];
#pragma unroll
        for (int j = 0; j < 22; j++) {
            const float* row = &T[(r0 + j) * TS + c + 1];
            unsigned long long acc = 0ull;
#pragma unroll
            for (int t = 0; t < 7; t++) {
                float v = row[t];
                acc = ffma2(wp[t], pack2(v, v * v), acc);
            }
            ring[j % 7] = acc;
            if (j >= 6) {
                unsigned long long me = 0ull;
#pragma unroll
                for (int i = 0; i < 7; i++) me = ffma2(wp[i], ring[(j - 6 + i) % 7], me);
                float mu, e2; unpack2(me, mu, e2);
                float var = fmaxf(fabsf(e2 - mu * mu), 1e-30f);
                float sig = fsqrt_ap(var);
                int rloc = r0 + j - 6;
                float x = T[(rloc + 3) * TS + (c + 4)];
                xn[rloc * 96 + c] = __float2half(fdiv_ap(x - mu, sig + 1.f));
            }
        }
        __syncthreads();
        aggd_features<96>(xn, 96, 9216.f, b, blk, 0, tid, s_wsum, s_tot, s_par);
    } else {
        // -------- scale 2: register-fused downsample + 48x48 --------
        int id2 = id - 3200;
        int b = id2 / 100, blk = id2 - 100 * b;
        int by0 = (blk / 10) * 48, bx0 = (blk % 10) * 48;
        float* Dh = sm;                    // 109 x 54
        float* T2 = Dh + 109 * 54;         // 54 x 54 (center -> xn)
        float* rX = T2 + 54 * 54;          // 54 x 48
        float* rX2 = rX + 54 * 48;         // 54 x 48
        const float* im = X + (size_t)b * HW1 * HW1;
        float w[7];
#pragma unroll
        for (int j = 0; j < 7; j++) w[j] = g_w7[j];
        float w3a = g_w3[0], w3b = g_w3[1], w3c = g_w3[2];
        int rbase = 2 * by0 - 7;

        if (bx0 != 0 && bx0 != 432) {
            int astart2 = 2 * bx0 - 8;
            for (int i = warp; i < 109; i += NW) {
                int ri = rbase + i;
                if (ri >= 0 && ri < 960) {
                    float4 v = make_float4(0.f, 0.f, 0.f, 0.f);
                    if (lane < 28)
                        v = __ldg((const float4*)(im + (size_t)ri * HW1 + astart2) + lane);
                    float nx = __shfl_down_sync(0xffffffffu, v.x, 1);
                    float ny = __shfl_down_sync(0xffffffffu, v.y, 1);
                    if (lane < 27) {
                        float o0 = fmaf(w3a, v.y, fmaf(w3b, v.z, w3c * v.w));
                        float o1 = fmaf(w3a, v.w, fmaf(w3b, nx, w3c * ny));
                        *(float2*)&Dh[i * 54 + 2 * lane] = make_float2(o0, o1);
                    }
                } else {
                    for (int k2 = lane; k2 < 54; k2 += 32) Dh[i * 54 + k2] = 0.f;
                }
            }
        } else {
            for (int idx = tid; idx < 109 * 54; idx += NTHR) {
                int i = idx / 54, cc = idx - 54 * i;
                int ri = rbase + i;
                float s = 0.f;
                if (ri >= 0 && ri < 960) {
                    int gxc = bx0 + cc - 3; gxc = gxc < 0 ? 0 : (gxc > 479 ? 479 : gxc);
                    int sx = 2 * gxc - 1;
                    const float* rp = &im[(size_t)ri * HW1];
                    if (sx >= 0) s = fmaf(w3a, __ldg(&rp[sx]), s);
                    s = fmaf(w3b, __ldg(&rp[sx + 1]), s);
                    if (sx + 2 < 960) s = fmaf(w3c, __ldg(&rp[sx + 2]), s);
                }
                Dh[idx] = s;
            }
        }
        __syncthreads();
        for (int idx = tid; idx < 54 * 54; idx += NTHR) {
            int r = idx / 54, cc = idx - 54 * r;
            int gyc = by0 + r - 3; gyc = gyc < 0 ? 0 : (gyc > 479 ? 479 : gyc);
            int row0 = 2 * (gyc - by0) + 6;
            const float* p = &Dh[row0 * 54 + cc];
            T2[idx] = fmaf(w3a, p[0], fmaf(w3b, p[54], w3c * p[108]));
        }
        __syncthreads();
        for (int idx = tid; idx < 54 * 48; idx += NTHR) {
            int r = idx / 48, cc = idx - 48 * r;
            const float* tr = &T2[r * 54 + cc];
            float a1 = 0.f, a2 = 0.f;
#pragma unroll
            for (int t = 0; t < 7; t++) {
                float v = tr[t];
                a1 = fmaf(w[t], v, a1);
                a2 = fmaf(w[t], v * v, a2);
            }
            rX[idx] = a1; rX2[idx] = a2;
        }
        __syncthreads();
        for (int idx = tid; idx < 48 * 48; idx += NTHR) {
            int r = idx / 48, cc = idx - 48 * r;
            float mu = 0.f, e2 = 0.f;
#pragma unroll
            for (int i = 0; i < 7; i++) {
                mu = fmaf(w[i], rX[(r + i) * 48 + cc], mu);
                e2 = fmaf(w[i], rX2[(r + i) * 48 + cc], e2);
            }
            float var = fmaxf(fabsf(e2 - mu * mu), 1e-30f);
            float sig = fsqrt_ap(var);
            int ctr = (r + 3) * 54 + cc + 3;
            T2[ctr] = fdiv_ap(T2[ctr] - mu, sig + 1.f);
        }
        __syncthreads();
        aggd_features<48>(&T2[3 * 54 + 3], 54, 2304.f, b, blk, 18, tid, s_wsum, s_tot, s_par);
    }
}

// ---------------- final: cov (block-parallel) + warp-0 unrolled Cholesky --------
__global__ __launch_bounds__(256) void final_kernel(const float* __restrict__ mu_pris,
                                                    const float* __restrict__ cov_pris,
                                                    float* __restrict__ out) {
    __shared__ float sd[100 * 36];
    __shared__ float sM[36 * 37];
    __shared__ float smu[36], sdiff[36], sz[36];
    int b = blockIdx.x, tid = threadIdx.x;
    const int NT = 256;
    const float* fb = &g_feats[(size_t)b * 100 * 36];
    for (int i = tid; i < 3600; i += NT) sd[i] = fb[i];
    __syncthreads();
    if (tid < 36) {
        float s = 0.f;
        for (int n = 0; n < 100; n++) s += sd[n * 36 + tid];
        float m = s / 100.0f;
        smu[tid] = m;
        sdiff[tid] = mu_pris[tid] - m;
    }
    __syncthreads();
    for (int idx = tid; idx < 1296; idx += NT) {
        int f = idx / 36, g = idx - f * 36;
        if (g < f) continue;
        float mf = smu[f], mg = smu[g];
        float a0 = 0.f, a1 = 0.f, a2 = 0.f, a3 = 0.f;
        for (int n = 0; n < 100; n += 4) {
            a0 = fmaf(sd[n * 36 + f] - mf, sd[n * 36 + g] - mg, a0);
            a1 = fmaf(sd[(n + 1) * 36 + f] - mf, sd[(n + 1) * 36 + g] - mg, a1);
            a2 = fmaf(sd[(n + 2) * 36 + f] - mf, sd[(n + 2) * 36 + g] - mg, a2);
            a3 = fmaf(sd[(n + 3) * 36 + f] - mf, sd[(n + 3) * 36 + g] - mg, a3);
        }
        float s = ((a0 + a1) + (a2 + a3)) / 99.0f;
        float m = 0.5f * (cov_pris[idx] + s);
        sM[f * 37 + g] = m;
        sM[g * 37 + f] = m;
    }
    __syncthreads();
    // warp 0: Cholesky + fused forward solve; inner products 4-way unrolled so
    // 4 independent LDS+FMA chains are in flight (dynamic-bound loops don't unroll
    // on their own — this was the 35us latency bug).
    if (tid < 32) {
        int lane = tid;
        for (int j = 0; j < 36; j++) {
            float pd = 0.f, pz = 0.f;
            for (int k = lane; k < j; k += 32) {
                float l = sM[j * 37 + k];
                pd = fmaf(l, l, pd);
                pz = fmaf(l, sz[k], pz);
            }
#pragma unroll
            for (int off = 16; off > 0; off >>= 1) {
                pd += __shfl_down_sync(0xffffffffu, pd, off);
                pz += __shfl_down_sync(0xffffffffu, pz, off);
            }
            if (lane == 0) {
                float d = sqrtf(fmaxf(sM[j * 37 + j] - pd, 1e-20f));
                sM[j * 37 + j] = d;
                sz[j] = (sdiff[j] - pz) / d;
            }
            __syncwarp();
            float dj = sM[j * 37 + j];
            for (int i = j + 1 + lane; i < 36; i += 32) {
                const float* ri = &sM[i * 37];
                const float* rj = &sM[j * 37];
                float t0 = 0.f, t1 = 0.f, t2 = 0.f, t3 = 0.f;
                int k = 0;
                for (; k + 4 <= j; k += 4) {
                    t0 = fmaf(ri[k + 0], rj[k + 0], t0);
                    t1 = fmaf(ri[k + 1], rj[k + 1], t1);
                    t2 = fmaf(ri[k + 2], rj[k + 2], t2);
                    t3 = fmaf(ri[k + 3], rj[k + 3], t3);
                }
                for (; k < j; k++) t0 = fmaf(ri[k], rj[k], t0);
                float s = sM[i * 37 + j] - ((t0 + t1) + (t2 + t3));
                sM[i * 37 + j] = s / dj;
            }
            __syncwarp();
        }
        if (lane == 0) {
            float q = 0.f;
            for (int i = 0; i < 36; i++) q += sz[i] * sz[i];
            out[b] = sqrtf(fmaxf(q, 0.f));
        }
    }
}

// ---------------- launch ----------------
extern "C" void kernel_launch(void* const* d_in, const int* in_sizes, int n_in,
                              void* d_out, int out_size) {
    (void)in_sizes; (void)n_in; (void)out_size;
    const float* X = (const float*)d_in[0];
    const float* mu_pris = (const float*)d_in[1];
    const float* cov_pris = (const float*)d_in[2];
    float* out = (float*)d_out;

    const size_t smB = (size_t)(102 * 104) * sizeof(float) + (size_t)(96 * 96) * sizeof(__half);
    cudaFuncSetAttribute(feat_kernel, cudaFuncAttributeMaxDynamicSharedMemorySize, (int)smB);

    init_tables_kernel<<<(NTAB + 511) / 512, 512>>>();
    feat_kernel<<<6400, NTHR, smB>>>(X);
    final_kernel<<<BATCH, 256>>>(mu_pris, cov_pris, out);
}